// round 1
// baseline (speedup 1.0000x reference)
#include <cuda_runtime.h>
#include <math.h>

#define HEADS 8
#define BATCH 4
#define CH    512
#define NTOK  2304          // 48*48
#define DQ    64

// Scratch (allocation-free rule: __device__ globals)
__device__ float g_Q [BATCH * CH * NTOK];
__device__ float g_K [BATCH * CH * NTOK];
__device__ float g_V [BATCH * CH * NTOK];
__device__ float g_SC[BATCH * CH * NTOK];

// ---------------------------------------------------------------------------
// Kernel A: 1x1-conv projections as GEMM.
// out[b][o][n] = sum_c W[o][c] * x[b][c][n]
// grid: (NTOK/128=18, CH/128=4, BATCH*4=16), block 256 (16x16), 8x8 microtile.
// ---------------------------------------------------------------------------
__global__ __launch_bounds__(256) void proj_kernel(
    const float* __restrict__ x,
    const float* __restrict__ Wq, const float* __restrict__ Wk,
    const float* __restrict__ Wv, const float* __restrict__ Wsc)
{
    const int which = blockIdx.z & 3;
    const int b     = blockIdx.z >> 2;
    const float* W  = (which == 0) ? Wq : (which == 1) ? Wk : (which == 2) ? Wv : Wsc;
    float* out      = (which == 0) ? g_Q : (which == 1) ? g_K : (which == 2) ? g_V : g_SC;

    const int n0 = blockIdx.x * 128;
    const int o0 = blockIdx.y * 128;
    const float* xb = x   + (size_t)b * CH * NTOK;
    float*       ob = out + (size_t)b * CH * NTOK;

    __shared__ float As[8][128];   // As[k][o]
    __shared__ float Bs[8][128];   // Bs[k][n]

    const int tid = threadIdx.x;
    const int tx = tid & 15;       // n dimension
    const int ty = tid >> 4;       // o dimension

    float acc[8][8];
#pragma unroll
    for (int i = 0; i < 8; i++)
#pragma unroll
        for (int j = 0; j < 8; j++) acc[i][j] = 0.f;

    for (int k0 = 0; k0 < CH; k0 += 8) {
        // A tile: W[o0+r][k0+c], 128x8, stored transposed
        {
            const int r = tid >> 1;
            const int c = (tid & 1) * 4;
            float4 v = *(const float4*)&W[(size_t)(o0 + r) * CH + k0 + c];
            As[c + 0][r] = v.x; As[c + 1][r] = v.y;
            As[c + 2][r] = v.z; As[c + 3][r] = v.w;
        }
        // B tile: x[b][k0+kk][n0 + j], 8x128
        {
            const int kk = tid >> 5;
            const int j  = (tid & 31) * 4;
            *(float4*)&Bs[kk][j] = *(const float4*)&xb[(size_t)(k0 + kk) * NTOK + n0 + j];
        }
        __syncthreads();

#pragma unroll
        for (int kk = 0; kk < 8; kk++) {
            float4 a0 = *(float4*)&As[kk][ty * 8];
            float4 a1 = *(float4*)&As[kk][ty * 8 + 4];
            float4 b0 = *(float4*)&Bs[kk][tx * 8];
            float4 b1 = *(float4*)&Bs[kk][tx * 8 + 4];
            float a[8] = {a0.x, a0.y, a0.z, a0.w, a1.x, a1.y, a1.z, a1.w};
            float bb[8] = {b0.x, b0.y, b0.z, b0.w, b1.x, b1.y, b1.z, b1.w};
#pragma unroll
            for (int i = 0; i < 8; i++)
#pragma unroll
                for (int j = 0; j < 8; j++) acc[i][j] += a[i] * bb[j];
        }
        __syncthreads();
    }

#pragma unroll
    for (int i = 0; i < 8; i++) {
        float4* p = (float4*)&ob[(size_t)(o0 + ty * 8 + i) * NTOK + n0 + tx * 8];
        p[0] = make_float4(acc[i][0], acc[i][1], acc[i][2], acc[i][3]);
        p[1] = make_float4(acc[i][4], acc[i][5], acc[i][6], acc[i][7]);
    }
}

// ---------------------------------------------------------------------------
// Kernel B: flash attention + fused epilogue (gamma*out + sc).
// grid: (36 q-tiles, HEADS, BATCH), block 256 (16x16).
// Q tile 64x64 resident; loop over 36 K/V tiles of 64.
// ---------------------------------------------------------------------------
#define VS_STRIDE 68
#define ATTN_SMEM_BYTES ((64*64 + 64*64 + 64*VS_STRIDE + 64*64) * 4)

__global__ __launch_bounds__(256) void attn_kernel(
    const float* __restrict__ gamma, float* __restrict__ outp)
{
    extern __shared__ float smem[];
    float (*Qs)[64]        = (float(*)[64])        smem;                    // [d][q]
    float (*Ks)[64]        = (float(*)[64])        (smem + 64 * 64);        // [d][m]
    float (*Vs)[VS_STRIDE] = (float(*)[VS_STRIDE]) (smem + 2 * 64 * 64);    // [dv][m]
    float (*Ps)[64]        = (float(*)[64])        (smem + 2 * 64 * 64 + 64 * VS_STRIDE); // [q][m]

    const int q0 = blockIdx.x * 64;
    const int h  = blockIdx.y;
    const int b  = blockIdx.z;

    const float* Q  = g_Q  + ((size_t)b * CH + h * DQ) * NTOK;
    const float* K  = g_K  + ((size_t)b * CH + h * DQ) * NTOK;
    const float* V  = g_V  + ((size_t)b * CH + h * DQ) * NTOK;
    const float* SC = g_SC + ((size_t)b * CH + h * DQ) * NTOK;

    const int tid = threadIdx.x;
    const int tx = tid & 15;       // key / dv dimension
    const int ty = tid >> 4;       // query dimension

    // Load Q tile: Qs[d][qi]
    for (int i = tid; i < 1024; i += 256) {
        const int d  = i >> 4;
        const int q4 = (i & 15) * 4;
        *(float4*)&Qs[d][q4] = *(const float4*)&Q[(size_t)d * NTOK + q0 + q4];
    }

    float m_i[4], l_i[4], acc[4][4];
#pragma unroll
    for (int r = 0; r < 4; r++) {
        m_i[r] = -1e30f; l_i[r] = 0.f;
#pragma unroll
        for (int c = 0; c < 4; c++) acc[r][c] = 0.f;
    }

    for (int kt = 0; kt < NTOK / 64; kt++) {
        const int m0 = kt * 64;
        // Load K and V tiles
        for (int i = tid; i < 1024; i += 256) {
            const int d  = i >> 4;
            const int m4 = (i & 15) * 4;
            *(float4*)&Ks[d][m4] = *(const float4*)&K[(size_t)d * NTOK + m0 + m4];
            *(float4*)&Vs[d][m4] = *(const float4*)&V[(size_t)d * NTOK + m0 + m4];
        }
        __syncthreads();

        // GEMM1: s[r][c] = sum_d Qs[d][ty*4+r] * Ks[d][tx*4+c]
        float s[4][4];
#pragma unroll
        for (int r = 0; r < 4; r++)
#pragma unroll
            for (int c = 0; c < 4; c++) s[r][c] = 0.f;

#pragma unroll 8
        for (int d = 0; d < 64; d++) {
            float4 a  = *(float4*)&Qs[d][ty * 4];
            float4 bq = *(float4*)&Ks[d][tx * 4];
            const float av[4] = {a.x, a.y, a.z, a.w};
            const float bv[4] = {bq.x, bq.y, bq.z, bq.w};
#pragma unroll
            for (int r = 0; r < 4; r++)
#pragma unroll
                for (int c = 0; c < 4; c++) s[r][c] += av[r] * bv[c];
        }

        // Online softmax (reduction across the 16 tx lanes; lanes with same ty
        // occupy one aligned 16-lane half-warp, so xor offsets 8..1 stay inside it)
#pragma unroll
        for (int r = 0; r < 4; r++) {
            float rmax = fmaxf(fmaxf(s[r][0], s[r][1]), fmaxf(s[r][2], s[r][3]));
#pragma unroll
            for (int off = 8; off >= 1; off >>= 1)
                rmax = fmaxf(rmax, __shfl_xor_sync(0xffffffffu, rmax, off));

            const float m_new = fmaxf(m_i[r], rmax);
            const float alpha = __expf(m_i[r] - m_new);
            float p[4], rsum = 0.f;
#pragma unroll
            for (int c = 0; c < 4; c++) {
                p[c] = __expf(s[r][c] - m_new);
                rsum += p[c];
            }
#pragma unroll
            for (int off = 8; off >= 1; off >>= 1)
                rsum += __shfl_xor_sync(0xffffffffu, rsum, off);

            l_i[r] = l_i[r] * alpha + rsum;
            m_i[r] = m_new;
#pragma unroll
            for (int c = 0; c < 4; c++) acc[r][c] *= alpha;
            *(float4*)&Ps[ty * 4 + r][tx * 4] = make_float4(p[0], p[1], p[2], p[3]);
        }
        __syncthreads();

        // GEMM2: acc[r][c] += sum_m Ps[ty*4+r][m] * Vs[tx*4+c][m]
#pragma unroll 4
        for (int kk = 0; kk < 64; kk += 4) {
            float4 pr[4], vv[4];
#pragma unroll
            for (int r = 0; r < 4; r++) pr[r] = *(float4*)&Ps[ty * 4 + r][kk];
#pragma unroll
            for (int c = 0; c < 4; c++) vv[c] = *(float4*)&Vs[tx * 4 + c][kk];
#pragma unroll
            for (int r = 0; r < 4; r++) {
#pragma unroll
                for (int c = 0; c < 4; c++) {
                    acc[r][c] += pr[r].x * vv[c].x + pr[r].y * vv[c].y +
                                 pr[r].z * vv[c].z + pr[r].w * vv[c].w;
                }
            }
        }
        __syncthreads();
    }

    // Epilogue: out[b][h*64+dv][q] = gamma[ch] * (acc/l) + sc
#pragma unroll
    for (int r = 0; r < 4; r++) {
        const float inv = 1.0f / l_i[r];
        const int q = q0 + ty * 4 + r;
#pragma unroll
        for (int c = 0; c < 4; c++) {
            const int dv = tx * 4 + c;
            const int ch = h * DQ + dv;
            const float o = acc[r][c] * inv;
            outp[((size_t)b * CH + ch) * NTOK + q] =
                gamma[ch] * o + SC[(size_t)dv * NTOK + q];
        }
    }
}

// ---------------------------------------------------------------------------
extern "C" void kernel_launch(void* const* d_in, const int* in_sizes, int n_in,
                              void* d_out, int out_size)
{
    const float* x     = (const float*)d_in[0];
    const float* Wq    = (const float*)d_in[1];
    const float* Wk    = (const float*)d_in[2];
    const float* Wv    = (const float*)d_in[3];
    const float* Wsc   = (const float*)d_in[4];
    const float* gamma = (const float*)d_in[5];
    float* out = (float*)d_out;

    dim3 g1(NTOK / 128, CH / 128, BATCH * 4);
    proj_kernel<<<g1, 256>>>(x, Wq, Wk, Wv, Wsc);

    cudaFuncSetAttribute(attn_kernel, cudaFuncAttributeMaxDynamicSharedMemorySize,
                         ATTN_SMEM_BYTES);
    dim3 g2(NTOK / 64, HEADS, BATCH);
    attn_kernel<<<g2, 256, ATTN_SMEM_BYTES>>>(gamma, out);
}

// round 3
// speedup vs baseline: 1.7203x; 1.7203x over previous
#include <cuda_runtime.h>
#include <math.h>
#include <stdint.h>

#define HEADS 8
#define BATCH 4
#define CH    512
#define NTOK  2304          // 48*48
#define DQ    64
#define QT    128
#define MT    128
#define NKT   (NTOK / MT)   // 18
#define PS_STRIDE 132

// Scratch (allocation-free rule: __device__ globals)
__device__ float g_Q [BATCH * CH * NTOK];
__device__ float g_K [BATCH * CH * NTOK];
__device__ float g_V [BATCH * CH * NTOK];
__device__ float g_SC[BATCH * CH * NTOK];
__device__ float g_Vt[BATCH * HEADS * NTOK * DQ];   // [b][h][n][dv]

// ---------------------------------------------------------------------------
// cp.async helpers
// ---------------------------------------------------------------------------
__device__ __forceinline__ void cp_async16(uint32_t dst, const void* src) {
    asm volatile("cp.async.cg.shared.global [%0], [%1], 16;\n" :: "r"(dst), "l"(src));
}
__device__ __forceinline__ void cp_commit() {
    asm volatile("cp.async.commit_group;\n" ::);
}
template<int N> __device__ __forceinline__ void cp_wait() {
    asm volatile("cp.async.wait_group %0;\n" :: "n"(N));
}

// ---------------------------------------------------------------------------
// Kernel A: 1x1-conv projections as GEMM. out[b][o][n] = sum_c W[o][c]*x[b][c][n]
// ---------------------------------------------------------------------------
__global__ __launch_bounds__(256) void proj_kernel(
    const float* __restrict__ x,
    const float* __restrict__ Wq, const float* __restrict__ Wk,
    const float* __restrict__ Wv, const float* __restrict__ Wsc)
{
    const int which = blockIdx.z & 3;
    const int b     = blockIdx.z >> 2;
    const float* W  = (which == 0) ? Wq : (which == 1) ? Wk : (which == 2) ? Wv : Wsc;
    float* out      = (which == 0) ? g_Q : (which == 1) ? g_K : (which == 2) ? g_V : g_SC;

    const int n0 = blockIdx.x * 128;
    const int o0 = blockIdx.y * 128;
    const float* xb = x   + (size_t)b * CH * NTOK;
    float*       ob = out + (size_t)b * CH * NTOK;

    __shared__ float As[8][128];
    __shared__ float Bs[8][128];

    const int tid = threadIdx.x;
    const int tx = tid & 15;
    const int ty = tid >> 4;

    float acc[8][8];
#pragma unroll
    for (int i = 0; i < 8; i++)
#pragma unroll
        for (int j = 0; j < 8; j++) acc[i][j] = 0.f;

    for (int k0 = 0; k0 < CH; k0 += 8) {
        {
            const int r = tid >> 1;
            const int c = (tid & 1) * 4;
            float4 v = *(const float4*)&W[(size_t)(o0 + r) * CH + k0 + c];
            As[c + 0][r] = v.x; As[c + 1][r] = v.y;
            As[c + 2][r] = v.z; As[c + 3][r] = v.w;
        }
        {
            const int kk = tid >> 5;
            const int j  = (tid & 31) * 4;
            *(float4*)&Bs[kk][j] = *(const float4*)&xb[(size_t)(k0 + kk) * NTOK + n0 + j];
        }
        __syncthreads();

#pragma unroll
        for (int kk = 0; kk < 8; kk++) {
            float4 a0 = *(float4*)&As[kk][ty * 8];
            float4 a1 = *(float4*)&As[kk][ty * 8 + 4];
            float4 b0 = *(float4*)&Bs[kk][tx * 8];
            float4 b1 = *(float4*)&Bs[kk][tx * 8 + 4];
            float a[8]  = {a0.x, a0.y, a0.z, a0.w, a1.x, a1.y, a1.z, a1.w};
            float bb[8] = {b0.x, b0.y, b0.z, b0.w, b1.x, b1.y, b1.z, b1.w};
#pragma unroll
            for (int i = 0; i < 8; i++)
#pragma unroll
                for (int j = 0; j < 8; j++) acc[i][j] += a[i] * bb[j];
        }
        __syncthreads();
    }

#pragma unroll
    for (int i = 0; i < 8; i++) {
        float4* p = (float4*)&ob[(size_t)(o0 + ty * 8 + i) * NTOK + n0 + tx * 8];
        p[0] = make_float4(acc[i][0], acc[i][1], acc[i][2], acc[i][3]);
        p[1] = make_float4(acc[i][4], acc[i][5], acc[i][6], acc[i][7]);
    }
}

// ---------------------------------------------------------------------------
// V transpose: g_V [b][h*64+dv][n]  ->  g_Vt [b][h][n][dv]
// ---------------------------------------------------------------------------
__global__ void transpose_v_kernel()
{
    __shared__ float t[32][33];
    const int bh = blockIdx.z;          // b*8 + h
    const int n0 = blockIdx.x * 32;
    const int d0 = blockIdx.y * 32;
    const int b  = bh >> 3;
    const int h  = bh & 7;
    const float* src = g_V + ((size_t)b * CH + h * DQ + d0) * NTOK;
    float*       dst = g_Vt + (size_t)bh * NTOK * DQ;

    const int tx = threadIdx.x;         // 32
    const int ty = threadIdx.y;         // 8
#pragma unroll
    for (int i = 0; i < 32; i += 8)
        t[ty + i][tx] = src[(size_t)(ty + i) * NTOK + n0 + tx];
    __syncthreads();
#pragma unroll
    for (int i = 0; i < 32; i += 8)
        dst[(size_t)(n0 + ty + i) * DQ + d0 + tx] = t[tx][ty + i];
}

// ---------------------------------------------------------------------------
// Kernel B: flash attention, 128x128 score tiles, 8x8 score microtile,
// 8x4 output microtile (dv = tx*4), cp.async double buffering.
// grid: (NTOK/128=18, HEADS, BATCH), block 256 (16 tx x 16 ty).
// ---------------------------------------------------------------------------
#define ATTN_SMEM_FLOATS (8192 /*Q*/ + 16384 /*K dbl*/ + 16384 /*V dbl*/ + 128 * PS_STRIDE)
#define ATTN_SMEM_BYTES  (ATTN_SMEM_FLOATS * 4)

__global__ __launch_bounds__(256, 1) void attn_kernel(
    const float* __restrict__ gamma, float* __restrict__ outp)
{
    extern __shared__ float smem[];
    float* Qs = smem;                 // [64][128]   (d-major, q contiguous)
    float* Ks = smem + 8192;          // [2][64][128]
    float* Vs = smem + 24576;         // [2][128][64]
    float* Ps = smem + 40960;         // [128][PS_STRIDE]

    const int q0 = blockIdx.x * QT;
    const int h  = blockIdx.y;
    const int b  = blockIdx.z;

    const float* Q  = g_Q  + ((size_t)b * CH + h * DQ) * NTOK;
    const float* K  = g_K  + ((size_t)b * CH + h * DQ) * NTOK;
    const float* Vt = g_Vt + (size_t)(b * HEADS + h) * NTOK * DQ;
    const float* SC = g_SC + ((size_t)b * CH + h * DQ) * NTOK;

    const int tid = threadIdx.x;
    const int tx = tid & 15;          // m dimension (x8) in GEMM1, dv (x4) in GEMM2
    const int ty = tid >> 4;          // q dimension (x8)

    const uint32_t sbase = (uint32_t)__cvta_generic_to_shared(smem);

    auto load_kv = [&](int st, int m0) {
#pragma unroll
        for (int j = 0; j < 8; j++) {
            const int idx = tid + j * 256;
            const int d  = idx >> 5;
            const int c4 = (idx & 31) << 2;
            cp_async16(sbase + ((8192 + st * 8192 + d * 128 + c4) << 2),
                       K + (size_t)d * NTOK + m0 + c4);
            const int m  = idx >> 4;
            const int v4 = (idx & 15) << 2;
            cp_async16(sbase + ((24576 + st * 8192 + m * 64 + v4) << 2),
                       Vt + (size_t)(m0 + m) * 64 + v4);
        }
    };

    // stage 0 K/V in flight, then Q tile via plain loads
    load_kv(0, 0);
    cp_commit();
#pragma unroll
    for (int j = 0; j < 8; j++) {
        const int idx = tid + j * 256;
        const int d  = idx >> 5;
        const int c4 = (idx & 31) << 2;
        *(float4*)(Qs + d * 128 + c4) = *(const float4*)(Q + (size_t)d * NTOK + q0 + c4);
    }

    float m_i[8], l_i[8], acc[8][4];
#pragma unroll
    for (int r = 0; r < 8; r++) {
        m_i[r] = -1e30f; l_i[r] = 0.f;
#pragma unroll
        for (int c = 0; c < 4; c++) acc[r][c] = 0.f;
    }

    for (int kt = 0; kt < NKT; kt++) {
        const int st = kt & 1;
        if (kt + 1 < NKT) {
            load_kv(st ^ 1, (kt + 1) * MT);
            cp_commit();
            cp_wait<1>();
        } else {
            cp_wait<0>();
        }
        __syncthreads();

        // ---- GEMM1: s[q][m] = sum_d Q[d][q] K[d][m]
        const float* Kst = Ks + st * 8192;
        float s[8][8];
#pragma unroll
        for (int r = 0; r < 8; r++)
#pragma unroll
            for (int c = 0; c < 8; c++) s[r][c] = 0.f;

#pragma unroll 4
        for (int d = 0; d < 64; d++) {
            float4 a0 = *(const float4*)(Qs + d * 128 + ty * 8);
            float4 a1 = *(const float4*)(Qs + d * 128 + ty * 8 + 4);
            float4 b0 = *(const float4*)(Kst + d * 128 + tx * 8);
            float4 b1 = *(const float4*)(Kst + d * 128 + tx * 8 + 4);
            const float av[8] = {a0.x, a0.y, a0.z, a0.w, a1.x, a1.y, a1.z, a1.w};
            const float bv[8] = {b0.x, b0.y, b0.z, b0.w, b1.x, b1.y, b1.z, b1.w};
#pragma unroll
            for (int r = 0; r < 8; r++)
#pragma unroll
                for (int c = 0; c < 8; c++) s[r][c] += av[r] * bv[c];
        }

        // ---- online softmax (row over 8 local cols + 16 tx lanes of half-warp)
#pragma unroll
        for (int r = 0; r < 8; r++) {
            float rmax = s[r][0];
#pragma unroll
            for (int c = 1; c < 8; c++) rmax = fmaxf(rmax, s[r][c]);
#pragma unroll
            for (int off = 8; off >= 1; off >>= 1)
                rmax = fmaxf(rmax, __shfl_xor_sync(0xffffffffu, rmax, off));

            const float m_new = fmaxf(m_i[r], rmax);
            const float alpha = __expf(m_i[r] - m_new);
            float rsum = 0.f;
#pragma unroll
            for (int c = 0; c < 8; c++) {
                s[r][c] = __expf(s[r][c] - m_new);
                rsum += s[r][c];
            }
#pragma unroll
            for (int off = 8; off >= 1; off >>= 1)
                rsum += __shfl_xor_sync(0xffffffffu, rsum, off);

            l_i[r] = l_i[r] * alpha + rsum;
            m_i[r] = m_new;
#pragma unroll
            for (int c = 0; c < 4; c++) acc[r][c] *= alpha;

            float* pr = Ps + (ty * 8 + r) * PS_STRIDE + tx * 8;
            *(float4*)pr       = make_float4(s[r][0], s[r][1], s[r][2], s[r][3]);
            *(float4*)(pr + 4) = make_float4(s[r][4], s[r][5], s[r][6], s[r][7]);
        }
        __syncwarp();   // P rows are produced & consumed within the same half-warp

        // ---- GEMM2: acc[q][dv] += sum_m P[q][m] V[m][dv],  dv = tx*4 + c
        const float* Vst = Vs + st * 8192;
#pragma unroll 2
        for (int m4 = 0; m4 < 32; m4++) {
            float4 pa[8];
#pragma unroll
            for (int r = 0; r < 8; r++)
                pa[r] = *(const float4*)(Ps + (ty * 8 + r) * PS_STRIDE + m4 * 4);
#pragma unroll
            for (int mm = 0; mm < 4; mm++) {
                float4 v = *(const float4*)(Vst + (m4 * 4 + mm) * 64 + tx * 4);
                const float vv[4] = {v.x, v.y, v.z, v.w};
#pragma unroll
                for (int r = 0; r < 8; r++) {
                    const float p = ((const float*)&pa[r])[mm];
#pragma unroll
                    for (int c = 0; c < 4; c++) acc[r][c] += p * vv[c];
                }
            }
        }
        __syncthreads();  // protect K/V buffers + Ps for next iteration
    }

    // ---- epilogue: out = gamma * (acc / l) + sc,  dv = tx*4 + c  (< 64)
    float invl[8];
#pragma unroll
    for (int r = 0; r < 8; r++) invl[r] = 1.0f / l_i[r];

#pragma unroll
    for (int c = 0; c < 4; c++) {
        const int dv = tx * 4 + c;
        const int ch = h * DQ + dv;
        const float g = gamma[ch];
        const float* scp = SC + (size_t)dv * NTOK + q0 + ty * 8;
        float4 s0 = *(const float4*)scp;
        float4 s1 = *(const float4*)(scp + 4);
        float* op = outp + ((size_t)b * CH + ch) * NTOK + q0 + ty * 8;
        float4 o0 = make_float4(g * acc[0][c] * invl[0] + s0.x,
                                g * acc[1][c] * invl[1] + s0.y,
                                g * acc[2][c] * invl[2] + s0.z,
                                g * acc[3][c] * invl[3] + s0.w);
        float4 o1 = make_float4(g * acc[4][c] * invl[4] + s1.x,
                                g * acc[5][c] * invl[5] + s1.y,
                                g * acc[6][c] * invl[6] + s1.z,
                                g * acc[7][c] * invl[7] + s1.w);
        *(float4*)op       = o0;
        *(float4*)(op + 4) = o1;
    }
}

// ---------------------------------------------------------------------------
extern "C" void kernel_launch(void* const* d_in, const int* in_sizes, int n_in,
                              void* d_out, int out_size)
{
    const float* x     = (const float*)d_in[0];
    const float* Wq    = (const float*)d_in[1];
    const float* Wk    = (const float*)d_in[2];
    const float* Wv    = (const float*)d_in[3];
    const float* Wsc   = (const float*)d_in[4];
    const float* gamma = (const float*)d_in[5];
    float* out = (float*)d_out;

    dim3 g1(NTOK / 128, CH / 128, BATCH * 4);
    proj_kernel<<<g1, 256>>>(x, Wq, Wk, Wv, Wsc);

    transpose_v_kernel<<<dim3(NTOK / 32, DQ / 32, BATCH * HEADS), dim3(32, 8)>>>();

    cudaFuncSetAttribute(attn_kernel, cudaFuncAttributeMaxDynamicSharedMemorySize,
                         ATTN_SMEM_BYTES);
    dim3 g2(NTOK / QT, HEADS, BATCH);
    attn_kernel<<<g2, 256, ATTN_SMEM_BYTES>>>(gamma, out);
}

// round 5
// speedup vs baseline: 2.0840x; 1.2114x over previous
#include <cuda_runtime.h>
#include <cuda_bf16.h>
#include <math.h>
#include <stdint.h>

#define HEADS 8
#define BATCH 4
#define CH    512
#define NTOK  2304          // 48*48
#define DQ    64
#define QT    128
#define MT    128
#define NKT   (NTOK / MT)   // 18
#define PS_STRIDE 132

// Scratch (allocation-free rule: __device__ globals)
__device__ float g_Q [BATCH * CH * NTOK];
__device__ float g_K [BATCH * CH * NTOK];
__device__ float g_V [BATCH * CH * NTOK];
__device__ float g_SC[BATCH * CH * NTOK];
__device__ float g_Vt[BATCH * HEADS * NTOK * DQ];       // [b][h][n][dv]
__device__ __nv_bfloat16 g_Wh [4 * CH * CH];            // [which][o][c] hi
__device__ __nv_bfloat16 g_Wl [4 * CH * CH];            // lo
__device__ __nv_bfloat16 g_xth[BATCH * NTOK * CH];      // [b][n][c] hi
__device__ __nv_bfloat16 g_xtl[BATCH * NTOK * CH];      // lo

// ---------------------------------------------------------------------------
// PTX helpers (compute_100-safe only: cp.async, ldmatrix, mma.sync)
// ---------------------------------------------------------------------------
__device__ __forceinline__ void cp_async16(uint32_t dst, const void* src) {
    asm volatile("cp.async.cg.shared.global [%0], [%1], 16;\n" :: "r"(dst), "l"(src));
}
__device__ __forceinline__ void cp_commit() {
    asm volatile("cp.async.commit_group;\n" ::);
}
template<int N> __device__ __forceinline__ void cp_wait() {
    asm volatile("cp.async.wait_group %0;\n" :: "n"(N));
}
__device__ __forceinline__ uint32_t smem_u32(const void* p) {
    return (uint32_t)__cvta_generic_to_shared(p);
}
__device__ __forceinline__ void ldsm4(uint32_t& r0, uint32_t& r1, uint32_t& r2,
                                      uint32_t& r3, uint32_t a) {
    asm volatile("ldmatrix.sync.aligned.m8n8.x4.shared.b16 {%0,%1,%2,%3}, [%4];"
                 : "=r"(r0), "=r"(r1), "=r"(r2), "=r"(r3) : "r"(a));
}
__device__ __forceinline__ void ldsm2(uint32_t& r0, uint32_t& r1, uint32_t a) {
    asm volatile("ldmatrix.sync.aligned.m8n8.x2.shared.b16 {%0,%1}, [%2];"
                 : "=r"(r0), "=r"(r1) : "r"(a));
}
__device__ __forceinline__ void mma_bf16(float& c0, float& c1, float& c2, float& c3,
                                         uint32_t a0, uint32_t a1, uint32_t a2, uint32_t a3,
                                         uint32_t b0, uint32_t b1) {
    asm volatile("mma.sync.aligned.m16n8k16.row.col.f32.bf16.bf16.f32 "
                 "{%0,%1,%2,%3}, {%4,%5,%6,%7}, {%8,%9}, {%0,%1,%2,%3};"
                 : "+f"(c0), "+f"(c1), "+f"(c2), "+f"(c3)
                 : "r"(a0), "r"(a1), "r"(a2), "r"(a3), "r"(b0), "r"(b1));
}

// ---------------------------------------------------------------------------
// prep kernels: bf16 hi/lo split (W as-is; x transposed to [b][n][c])
// ---------------------------------------------------------------------------
__global__ void prep_w_kernel(const float* __restrict__ Wq, const float* __restrict__ Wk,
                              const float* __restrict__ Wv, const float* __restrict__ Wsc)
{
    const float* W = (blockIdx.y == 0) ? Wq : (blockIdx.y == 1) ? Wk
                   : (blockIdx.y == 2) ? Wv : Wsc;
    const int idx = blockIdx.x * 256 + threadIdx.x;
    const float a = W[idx];
    const __nv_bfloat16 h = __float2bfloat16(a);
    const size_t o = (size_t)blockIdx.y * CH * CH + idx;
    g_Wh[o] = h;
    g_Wl[o] = __float2bfloat16(a - __bfloat162float(h));
}

__global__ void prep_x_kernel(const float* __restrict__ x)
{
    __shared__ float t[32][33];
    const int b  = blockIdx.z;
    const int n0 = blockIdx.x * 32;
    const int c0 = blockIdx.y * 32;
    const int tx = threadIdx.x, ty = threadIdx.y;     // 32, 8
    const float* src = x + ((size_t)b * CH + c0) * NTOK + n0;
#pragma unroll
    for (int i = 0; i < 32; i += 8)
        t[ty + i][tx] = src[(size_t)(ty + i) * NTOK + tx];
    __syncthreads();
    __nv_bfloat16* dh = g_xth + ((size_t)b * NTOK + n0) * CH + c0;
    __nv_bfloat16* dl = g_xtl + ((size_t)b * NTOK + n0) * CH + c0;
#pragma unroll
    for (int i = 0; i < 32; i += 8) {
        const float v = t[tx][ty + i];
        const __nv_bfloat16 h = __float2bfloat16(v);
        dh[(size_t)(ty + i) * CH + tx] = h;
        dl[(size_t)(ty + i) * CH + tx] = __float2bfloat16(v - __bfloat162float(h));
    }
}

// ---------------------------------------------------------------------------
// Projection GEMM via mma.sync bf16 3-term split.
// D[o][n] = sum_c W[o][c] x_t[n][c] ; A = W (row-major, k=c), B = x_t (n rows, k=c)
// Block 128x128, 8 warps (2m x 4n), warp tile 64x32, K-chunks of 32, dbl-buffered.
// smem bf16 rows stride 40 elems (80 B): 16B-aligned, ldmatrix conflict-free.
// ---------------------------------------------------------------------------
#define PJ_ARR_BYTES   10240                  // 128 rows * 80 B
#define PJ_STAGE_BYTES (4 * PJ_ARR_BYTES)     // Ah | Al | Bh | Bl
#define PJ_SMEM_BYTES  (2 * PJ_STAGE_BYTES)   // 81920

__global__ __launch_bounds__(256, 1) void proj_mma_kernel(void)
{
    extern __shared__ char smem[];
    const uint32_t sbase = smem_u32(smem);
    const int tid = threadIdx.x;
    const int wid = tid >> 5;
    const int lid = tid & 31;

    const int which = blockIdx.z & 3;
    const int b     = blockIdx.z >> 2;
    const int n0    = blockIdx.x * 128;
    const int o0    = blockIdx.y * 128;

    const __nv_bfloat16* Ah_g = g_Wh + (size_t)which * CH * CH + (size_t)o0 * CH;
    const __nv_bfloat16* Al_g = g_Wl + (size_t)which * CH * CH + (size_t)o0 * CH;
    const __nv_bfloat16* Bh_g = g_xth + ((size_t)b * NTOK + n0) * CH;
    const __nv_bfloat16* Bl_g = g_xtl + ((size_t)b * NTOK + n0) * CH;
    float* outArr = (which == 0) ? g_Q : (which == 1) ? g_K : (which == 2) ? g_V : g_SC;
    float* outb = outArr + ((size_t)b * CH + o0) * NTOK + n0;

    const int warp_m = wid >> 2;              // 0..1  -> m offset 0/64
    const int warp_n = wid & 3;               // 0..3  -> n offset 0/32/64/96
    const int mbase = warp_m * 64;
    const int nbase = warp_n * 32;

    auto load_chunk = [&](int buf, int chunk) {
        const int c0 = chunk * 32;
        const uint32_t sb = sbase + buf * PJ_STAGE_BYTES;
#pragma unroll
        for (int t = 0; t < 8; t++) {
            const int idx = tid + t * 256;          // 0..2047
            const int arr = idx >> 9;               // 0..3
            const int i   = idx & 511;
            const int row = i >> 2;                 // 0..127
            const int q16 = (i & 3) * 16;           // byte offset in 64B row span
            const uint32_t dst = sb + arr * PJ_ARR_BYTES + row * 80 + q16;
            const __nv_bfloat16* base = (arr == 0) ? Ah_g : (arr == 1) ? Al_g
                                      : (arr == 2) ? Bh_g : Bl_g;
            cp_async16(dst, (const char*)(base + (size_t)row * CH + c0) + q16);
        }
        cp_commit();
    };

    float c[4][4][4];
#pragma unroll
    for (int mt = 0; mt < 4; mt++)
#pragma unroll
        for (int nt = 0; nt < 4; nt++)
#pragma unroll
            for (int k = 0; k < 4; k++) c[mt][nt][k] = 0.f;

    load_chunk(0, 0);

    for (int chunk = 0; chunk < 16; chunk++) {
        const int buf = chunk & 1;
        if (chunk + 1 < 16) {
            load_chunk(buf ^ 1, chunk + 1);
            cp_wait<1>();
        } else {
            cp_wait<0>();
        }
        __syncthreads();

        const uint32_t sb = sbase + buf * PJ_STAGE_BYTES;
        // A fragment address: lanes 0-7 m rows 0-7(k0), 8-15 m+8(k0), 16-23 m(k+8), 24-31 m+8(k+8)
        const int arow = (lid & 7) + ((lid & 8) ? 8 : 0);
        const int akob = (lid & 16) ? 16 : 0;     // +8 elems = 16 bytes
        // B fragment address (x2): lanes 0-7 n rows(k0), 8-15 n rows(k+8)
        const int brow = lid & 7;
        const int bkob = (lid & 8) ? 16 : 0;

#pragma unroll
        for (int kstep = 0; kstep < 2; kstep++) {
            const int kb = kstep * 32;            // 16 elems = 32 bytes

            uint32_t bh[4][2], bl[4][2];
#pragma unroll
            for (int nt = 0; nt < 4; nt++) {
                const uint32_t ba = sb + 2 * PJ_ARR_BYTES +
                                    (nbase + nt * 8 + brow) * 80 + bkob + kb;
                ldsm2(bh[nt][0], bh[nt][1], ba);
                ldsm2(bl[nt][0], bl[nt][1], ba + PJ_ARR_BYTES);
            }

#pragma unroll
            for (int mt = 0; mt < 4; mt++) {
                const uint32_t aa = sb + (mbase + mt * 16 + arow) * 80 + akob + kb;
                uint32_t ah[4], al[4];
                ldsm4(ah[0], ah[1], ah[2], ah[3], aa);
                ldsm4(al[0], al[1], al[2], al[3], aa + PJ_ARR_BYTES);
#pragma unroll
                for (int nt = 0; nt < 4; nt++) {
                    mma_bf16(c[mt][nt][0], c[mt][nt][1], c[mt][nt][2], c[mt][nt][3],
                             ah[0], ah[1], ah[2], ah[3], bh[nt][0], bh[nt][1]);
                    mma_bf16(c[mt][nt][0], c[mt][nt][1], c[mt][nt][2], c[mt][nt][3],
                             ah[0], ah[1], ah[2], ah[3], bl[nt][0], bl[nt][1]);
                    mma_bf16(c[mt][nt][0], c[mt][nt][1], c[mt][nt][2], c[mt][nt][3],
                             al[0], al[1], al[2], al[3], bh[nt][0], bh[nt][1]);
                }
            }
        }
        __syncthreads();
    }

    // Epilogue: c fragments -> global (float2 per quad, rows o, cols tokens)
#pragma unroll
    for (int mt = 0; mt < 4; mt++) {
#pragma unroll
        for (int nt = 0; nt < 4; nt++) {
            const int m = mbase + mt * 16 + (lid >> 2);
            const int nn = nbase + nt * 8 + 2 * (lid & 3);
            *(float2*)&outb[(size_t)m * NTOK + nn] =
                make_float2(c[mt][nt][0], c[mt][nt][1]);
            *(float2*)&outb[(size_t)(m + 8) * NTOK + nn] =
                make_float2(c[mt][nt][2], c[mt][nt][3]);
        }
    }
}

// ---------------------------------------------------------------------------
// V transpose: g_V [b][h*64+dv][n] -> g_Vt [b][h][n][dv]
// ---------------------------------------------------------------------------
__global__ void transpose_v_kernel()
{
    __shared__ float t[32][33];
    const int bh = blockIdx.z;
    const int n0 = blockIdx.x * 32;
    const int d0 = blockIdx.y * 32;
    const int b  = bh >> 3;
    const int h  = bh & 7;
    const float* src = g_V + ((size_t)b * CH + h * DQ + d0) * NTOK;
    float*       dst = g_Vt + (size_t)bh * NTOK * DQ;

    const int tx = threadIdx.x, ty = threadIdx.y;
#pragma unroll
    for (int i = 0; i < 32; i += 8)
        t[ty + i][tx] = src[(size_t)(ty + i) * NTOK + n0 + tx];
    __syncthreads();
#pragma unroll
    for (int i = 0; i < 32; i += 8)
        dst[(size_t)(n0 + ty + i) * DQ + d0 + tx] = t[tx][ty + i];
}

// ---------------------------------------------------------------------------
// Flash attention (unchanged R3 passing version)
// ---------------------------------------------------------------------------
#define ATTN_SMEM_FLOATS (8192 + 16384 + 16384 + 128 * PS_STRIDE)
#define ATTN_SMEM_BYTES  (ATTN_SMEM_FLOATS * 4)

__global__ __launch_bounds__(256, 1) void attn_kernel(
    const float* __restrict__ gamma, float* __restrict__ outp)
{
    extern __shared__ float smemf[];
    float* Qs = smemf;
    float* Ks = smemf + 8192;
    float* Vs = smemf + 24576;
    float* Ps = smemf + 40960;

    const int q0 = blockIdx.x * QT;
    const int h  = blockIdx.y;
    const int b  = blockIdx.z;

    const float* Q  = g_Q  + ((size_t)b * CH + h * DQ) * NTOK;
    const float* K  = g_K  + ((size_t)b * CH + h * DQ) * NTOK;
    const float* Vt = g_Vt + (size_t)(b * HEADS + h) * NTOK * DQ;
    const float* SC = g_SC + ((size_t)b * CH + h * DQ) * NTOK;

    const int tid = threadIdx.x;
    const int tx = tid & 15;
    const int ty = tid >> 4;

    const uint32_t sbase = smem_u32(smemf);

    auto load_kv = [&](int st, int m0) {
#pragma unroll
        for (int j = 0; j < 8; j++) {
            const int idx = tid + j * 256;
            const int d  = idx >> 5;
            const int c4 = (idx & 31) << 2;
            cp_async16(sbase + ((8192 + st * 8192 + d * 128 + c4) << 2),
                       K + (size_t)d * NTOK + m0 + c4);
            const int m  = idx >> 4;
            const int v4 = (idx & 15) << 2;
            cp_async16(sbase + ((24576 + st * 8192 + m * 64 + v4) << 2),
                       Vt + (size_t)(m0 + m) * 64 + v4);
        }
    };

    load_kv(0, 0);
    cp_commit();
#pragma unroll
    for (int j = 0; j < 8; j++) {
        const int idx = tid + j * 256;
        const int d  = idx >> 5;
        const int c4 = (idx & 31) << 2;
        *(float4*)(Qs + d * 128 + c4) = *(const float4*)(Q + (size_t)d * NTOK + q0 + c4);
    }

    float m_i[8], l_i[8], acc[8][4];
#pragma unroll
    for (int r = 0; r < 8; r++) {
        m_i[r] = -1e30f; l_i[r] = 0.f;
#pragma unroll
        for (int c = 0; c < 4; c++) acc[r][c] = 0.f;
    }

    for (int kt = 0; kt < NKT; kt++) {
        const int st = kt & 1;
        if (kt + 1 < NKT) {
            load_kv(st ^ 1, (kt + 1) * MT);
            cp_commit();
            cp_wait<1>();
        } else {
            cp_wait<0>();
        }
        __syncthreads();

        const float* Kst = Ks + st * 8192;
        float s[8][8];
#pragma unroll
        for (int r = 0; r < 8; r++)
#pragma unroll
            for (int c = 0; c < 8; c++) s[r][c] = 0.f;

#pragma unroll 4
        for (int d = 0; d < 64; d++) {
            float4 a0 = *(const float4*)(Qs + d * 128 + ty * 8);
            float4 a1 = *(const float4*)(Qs + d * 128 + ty * 8 + 4);
            float4 b0 = *(const float4*)(Kst + d * 128 + tx * 8);
            float4 b1 = *(const float4*)(Kst + d * 128 + tx * 8 + 4);
            const float av[8] = {a0.x, a0.y, a0.z, a0.w, a1.x, a1.y, a1.z, a1.w};
            const float bv[8] = {b0.x, b0.y, b0.z, b0.w, b1.x, b1.y, b1.z, b1.w};
#pragma unroll
            for (int r = 0; r < 8; r++)
#pragma unroll
                for (int c = 0; c < 8; c++) s[r][c] += av[r] * bv[c];
        }

#pragma unroll
        for (int r = 0; r < 8; r++) {
            float rmax = s[r][0];
#pragma unroll
            for (int c = 1; c < 8; c++) rmax = fmaxf(rmax, s[r][c]);
#pragma unroll
            for (int off = 8; off >= 1; off >>= 1)
                rmax = fmaxf(rmax, __shfl_xor_sync(0xffffffffu, rmax, off));

            const float m_new = fmaxf(m_i[r], rmax);
            const float alpha = __expf(m_i[r] - m_new);
            float rsum = 0.f;
#pragma unroll
            for (int c = 0; c < 8; c++) {
                s[r][c] = __expf(s[r][c] - m_new);
                rsum += s[r][c];
            }
#pragma unroll
            for (int off = 8; off >= 1; off >>= 1)
                rsum += __shfl_xor_sync(0xffffffffu, rsum, off);

            l_i[r] = l_i[r] * alpha + rsum;
            m_i[r] = m_new;
#pragma unroll
            for (int c = 0; c < 4; c++) acc[r][c] *= alpha;

            float* pr = Ps + (ty * 8 + r) * PS_STRIDE + tx * 8;
            *(float4*)pr       = make_float4(s[r][0], s[r][1], s[r][2], s[r][3]);
            *(float4*)(pr + 4) = make_float4(s[r][4], s[r][5], s[r][6], s[r][7]);
        }
        __syncwarp();

        const float* Vst = Vs + st * 8192;
#pragma unroll 2
        for (int m4 = 0; m4 < 32; m4++) {
            float4 pa[8];
#pragma unroll
            for (int r = 0; r < 8; r++)
                pa[r] = *(const float4*)(Ps + (ty * 8 + r) * PS_STRIDE + m4 * 4);
#pragma unroll
            for (int mm = 0; mm < 4; mm++) {
                float4 v = *(const float4*)(Vst + (m4 * 4 + mm) * 64 + tx * 4);
                const float vv[4] = {v.x, v.y, v.z, v.w};
#pragma unroll
                for (int r = 0; r < 8; r++) {
                    const float p = ((const float*)&pa[r])[mm];
#pragma unroll
                    for (int c = 0; c < 4; c++) acc[r][c] += p * vv[c];
                }
            }
        }
        __syncthreads();
    }

    float invl[8];
#pragma unroll
    for (int r = 0; r < 8; r++) invl[r] = 1.0f / l_i[r];

#pragma unroll
    for (int c = 0; c < 4; c++) {
        const int dv = tx * 4 + c;
        const int ch = h * DQ + dv;
        const float g = gamma[ch];
        const float* scp = SC + (size_t)dv * NTOK + q0 + ty * 8;
        float4 s0 = *(const float4*)scp;
        float4 s1 = *(const float4*)(scp + 4);
        float* op = outp + ((size_t)b * CH + ch) * NTOK + q0 + ty * 8;
        *(float4*)op = make_float4(g * acc[0][c] * invl[0] + s0.x,
                                   g * acc[1][c] * invl[1] + s0.y,
                                   g * acc[2][c] * invl[2] + s0.z,
                                   g * acc[3][c] * invl[3] + s0.w);
        *(float4*)(op + 4) = make_float4(g * acc[4][c] * invl[4] + s1.x,
                                         g * acc[5][c] * invl[5] + s1.y,
                                         g * acc[6][c] * invl[6] + s1.z,
                                         g * acc[7][c] * invl[7] + s1.w);
    }
}

// ---------------------------------------------------------------------------
extern "C" void kernel_launch(void* const* d_in, const int* in_sizes, int n_in,
                              void* d_out, int out_size)
{
    const float* x     = (const float*)d_in[0];
    const float* Wq    = (const float*)d_in[1];
    const float* Wk    = (const float*)d_in[2];
    const float* Wv    = (const float*)d_in[3];
    const float* Wsc   = (const float*)d_in[4];
    const float* gamma = (const float*)d_in[5];
    float* out = (float*)d_out;

    prep_w_kernel<<<dim3(CH * CH / 256, 4), 256>>>(Wq, Wk, Wv, Wsc);
    prep_x_kernel<<<dim3(NTOK / 32, CH / 32, BATCH), dim3(32, 8)>>>(x);

    cudaFuncSetAttribute(proj_mma_kernel, cudaFuncAttributeMaxDynamicSharedMemorySize,
                         PJ_SMEM_BYTES);
    proj_mma_kernel<<<dim3(NTOK / 128, CH / 128, 16), 256, PJ_SMEM_BYTES>>>();

    transpose_v_kernel<<<dim3(NTOK / 32, DQ / 32, BATCH * HEADS), dim3(32, 8)>>>();

    cudaFuncSetAttribute(attn_kernel, cudaFuncAttributeMaxDynamicSharedMemorySize,
                         ATTN_SMEM_BYTES);
    attn_kernel<<<dim3(NTOK / QT, HEADS, BATCH), 256, ATTN_SMEM_BYTES>>>(gamma, out);
}

// round 6
// speedup vs baseline: 4.0384x; 1.9379x over previous
#include <cuda_runtime.h>
#include <cuda_bf16.h>
#include <math.h>
#include <stdint.h>

#define HEADS 8
#define BATCH 4
#define CH    512
#define NTOK  2304          // 48*48
#define DQ    64

// Scratch (allocation-free rule: __device__ globals)
__device__ float g_Q [BATCH * CH * NTOK];
__device__ float g_K [BATCH * CH * NTOK];
__device__ float g_V [BATCH * CH * NTOK];
__device__ float g_SC[BATCH * CH * NTOK];
__device__ __nv_bfloat16 g_Wh [4 * CH * CH];
__device__ __nv_bfloat16 g_Wl [4 * CH * CH];
__device__ __nv_bfloat16 g_xth[BATCH * NTOK * CH];
__device__ __nv_bfloat16 g_xtl[BATCH * NTOK * CH];
// token-major bf16 hi/lo Q,K: [b][h][n][64]
__device__ __nv_bfloat16 g_Qth[BATCH * HEADS * NTOK * DQ];
__device__ __nv_bfloat16 g_Qtl[BATCH * HEADS * NTOK * DQ];
__device__ __nv_bfloat16 g_Kth[BATCH * HEADS * NTOK * DQ];
__device__ __nv_bfloat16 g_Ktl[BATCH * HEADS * NTOK * DQ];
// V split (layout identical to g_V): [b][ch][n]
__device__ __nv_bfloat16 g_Vh[BATCH * CH * NTOK];
__device__ __nv_bfloat16 g_Vl[BATCH * CH * NTOK];

// ---------------------------------------------------------------------------
// PTX helpers (compute_100-safe: cp.async, ldmatrix, mma.sync)
// ---------------------------------------------------------------------------
__device__ __forceinline__ void cp_async16(uint32_t dst, const void* src) {
    asm volatile("cp.async.cg.shared.global [%0], [%1], 16;\n" :: "r"(dst), "l"(src));
}
__device__ __forceinline__ void cp_commit() {
    asm volatile("cp.async.commit_group;\n" ::);
}
template<int N> __device__ __forceinline__ void cp_wait() {
    asm volatile("cp.async.wait_group %0;\n" :: "n"(N));
}
__device__ __forceinline__ uint32_t smem_u32(const void* p) {
    return (uint32_t)__cvta_generic_to_shared(p);
}
__device__ __forceinline__ void ldsm4(uint32_t& r0, uint32_t& r1, uint32_t& r2,
                                      uint32_t& r3, uint32_t a) {
    asm volatile("ldmatrix.sync.aligned.m8n8.x4.shared.b16 {%0,%1,%2,%3}, [%4];"
                 : "=r"(r0), "=r"(r1), "=r"(r2), "=r"(r3) : "r"(a));
}
__device__ __forceinline__ void ldsm2(uint32_t& r0, uint32_t& r1, uint32_t a) {
    asm volatile("ldmatrix.sync.aligned.m8n8.x2.shared.b16 {%0,%1}, [%2];"
                 : "=r"(r0), "=r"(r1) : "r"(a));
}
__device__ __forceinline__ void mma_bf16(float& c0, float& c1, float& c2, float& c3,
                                         uint32_t a0, uint32_t a1, uint32_t a2, uint32_t a3,
                                         uint32_t b0, uint32_t b1) {
    asm volatile("mma.sync.aligned.m16n8k16.row.col.f32.bf16.bf16.f32 "
                 "{%0,%1,%2,%3}, {%4,%5,%6,%7}, {%8,%9}, {%0,%1,%2,%3};"
                 : "+f"(c0), "+f"(c1), "+f"(c2), "+f"(c3)
                 : "r"(a0), "r"(a1), "r"(a2), "r"(a3), "r"(b0), "r"(b1));
}
__device__ __forceinline__ uint32_t pack_bf16x2(float lo, float hi) {
    uint32_t r;
    asm("cvt.rn.bf16x2.f32 %0, %1, %2;" : "=r"(r) : "f"(hi), "f"(lo));
    return r;
}

// ---------------------------------------------------------------------------
// prep kernels: bf16 hi/lo split of W; x transposed to [b][n][c] hi/lo
// ---------------------------------------------------------------------------
__global__ void prep_w_kernel(const float* __restrict__ Wq, const float* __restrict__ Wk,
                              const float* __restrict__ Wv, const float* __restrict__ Wsc)
{
    const float* W = (blockIdx.y == 0) ? Wq : (blockIdx.y == 1) ? Wk
                   : (blockIdx.y == 2) ? Wv : Wsc;
    const int idx = blockIdx.x * 256 + threadIdx.x;
    const float a = W[idx];
    const __nv_bfloat16 h = __float2bfloat16(a);
    const size_t o = (size_t)blockIdx.y * CH * CH + idx;
    g_Wh[o] = h;
    g_Wl[o] = __float2bfloat16(a - __bfloat162float(h));
}

__global__ void prep_x_kernel(const float* __restrict__ x)
{
    __shared__ float t[32][33];
    const int b  = blockIdx.z;
    const int n0 = blockIdx.x * 32;
    const int c0 = blockIdx.y * 32;
    const int tx = threadIdx.x, ty = threadIdx.y;
    const float* src = x + ((size_t)b * CH + c0) * NTOK + n0;
#pragma unroll
    for (int i = 0; i < 32; i += 8)
        t[ty + i][tx] = src[(size_t)(ty + i) * NTOK + tx];
    __syncthreads();
    __nv_bfloat16* dh = g_xth + ((size_t)b * NTOK + n0) * CH + c0;
    __nv_bfloat16* dl = g_xtl + ((size_t)b * NTOK + n0) * CH + c0;
#pragma unroll
    for (int i = 0; i < 32; i += 8) {
        const float v = t[tx][ty + i];
        const __nv_bfloat16 h = __float2bfloat16(v);
        dh[(size_t)(ty + i) * CH + tx] = h;
        dl[(size_t)(ty + i) * CH + tx] = __float2bfloat16(v - __bfloat162float(h));
    }
}

// ---------------------------------------------------------------------------
// Projection GEMM via mma.sync bf16 3-term split (proven in R5).
// ---------------------------------------------------------------------------
#define PJ_ARR_BYTES   10240
#define PJ_STAGE_BYTES (4 * PJ_ARR_BYTES)
#define PJ_SMEM_BYTES  (2 * PJ_STAGE_BYTES)

__global__ __launch_bounds__(256, 1) void proj_mma_kernel(void)
{
    extern __shared__ char smem[];
    const uint32_t sbase = smem_u32(smem);
    const int tid = threadIdx.x;
    const int wid = tid >> 5;
    const int lid = tid & 31;

    const int which = blockIdx.z & 3;
    const int b     = blockIdx.z >> 2;
    const int n0    = blockIdx.x * 128;
    const int o0    = blockIdx.y * 128;

    const __nv_bfloat16* Ah_g = g_Wh + (size_t)which * CH * CH + (size_t)o0 * CH;
    const __nv_bfloat16* Al_g = g_Wl + (size_t)which * CH * CH + (size_t)o0 * CH;
    const __nv_bfloat16* Bh_g = g_xth + ((size_t)b * NTOK + n0) * CH;
    const __nv_bfloat16* Bl_g = g_xtl + ((size_t)b * NTOK + n0) * CH;
    float* outArr = (which == 0) ? g_Q : (which == 1) ? g_K : (which == 2) ? g_V : g_SC;
    float* outb = outArr + ((size_t)b * CH + o0) * NTOK + n0;

    const int warp_m = wid >> 2;
    const int warp_n = wid & 3;
    const int mbase = warp_m * 64;
    const int nbase = warp_n * 32;

    auto load_chunk = [&](int buf, int chunk) {
        const int c0 = chunk * 32;
        const uint32_t sb = sbase + buf * PJ_STAGE_BYTES;
#pragma unroll
        for (int t = 0; t < 8; t++) {
            const int idx = tid + t * 256;
            const int arr = idx >> 9;
            const int i   = idx & 511;
            const int row = i >> 2;
            const int q16 = (i & 3) * 16;
            const uint32_t dst = sb + arr * PJ_ARR_BYTES + row * 80 + q16;
            const __nv_bfloat16* base = (arr == 0) ? Ah_g : (arr == 1) ? Al_g
                                      : (arr == 2) ? Bh_g : Bl_g;
            cp_async16(dst, (const char*)(base + (size_t)row * CH + c0) + q16);
        }
        cp_commit();
    };

    float c[4][4][4];
#pragma unroll
    for (int mt = 0; mt < 4; mt++)
#pragma unroll
        for (int nt = 0; nt < 4; nt++)
#pragma unroll
            for (int k = 0; k < 4; k++) c[mt][nt][k] = 0.f;

    load_chunk(0, 0);

    for (int chunk = 0; chunk < 16; chunk++) {
        const int buf = chunk & 1;
        if (chunk + 1 < 16) {
            load_chunk(buf ^ 1, chunk + 1);
            cp_wait<1>();
        } else {
            cp_wait<0>();
        }
        __syncthreads();

        const uint32_t sb = sbase + buf * PJ_STAGE_BYTES;
        const int arow = (lid & 7) + ((lid & 8) ? 8 : 0);
        const int akob = (lid & 16) ? 16 : 0;
        const int brow = lid & 7;
        const int bkob = (lid & 8) ? 16 : 0;

#pragma unroll
        for (int kstep = 0; kstep < 2; kstep++) {
            const int kb = kstep * 32;

            uint32_t bh[4][2], bl[4][2];
#pragma unroll
            for (int nt = 0; nt < 4; nt++) {
                const uint32_t ba = sb + 2 * PJ_ARR_BYTES +
                                    (nbase + nt * 8 + brow) * 80 + bkob + kb;
                ldsm2(bh[nt][0], bh[nt][1], ba);
                ldsm2(bl[nt][0], bl[nt][1], ba + PJ_ARR_BYTES);
            }

#pragma unroll
            for (int mt = 0; mt < 4; mt++) {
                const uint32_t aa = sb + (mbase + mt * 16 + arow) * 80 + akob + kb;
                uint32_t ah[4], al[4];
                ldsm4(ah[0], ah[1], ah[2], ah[3], aa);
                ldsm4(al[0], al[1], al[2], al[3], aa + PJ_ARR_BYTES);
#pragma unroll
                for (int nt = 0; nt < 4; nt++) {
                    mma_bf16(c[mt][nt][0], c[mt][nt][1], c[mt][nt][2], c[mt][nt][3],
                             ah[0], ah[1], ah[2], ah[3], bh[nt][0], bh[nt][1]);
                    mma_bf16(c[mt][nt][0], c[mt][nt][1], c[mt][nt][2], c[mt][nt][3],
                             ah[0], ah[1], ah[2], ah[3], bl[nt][0], bl[nt][1]);
                    mma_bf16(c[mt][nt][0], c[mt][nt][1], c[mt][nt][2], c[mt][nt][3],
                             al[0], al[1], al[2], al[3], bh[nt][0], bh[nt][1]);
                }
            }
        }
        __syncthreads();
    }

#pragma unroll
    for (int mt = 0; mt < 4; mt++) {
#pragma unroll
        for (int nt = 0; nt < 4; nt++) {
            const int m = mbase + mt * 16 + (lid >> 2);
            const int nn = nbase + nt * 8 + 2 * (lid & 3);
            *(float2*)&outb[(size_t)m * NTOK + nn] =
                make_float2(c[mt][nt][0], c[mt][nt][1]);
            *(float2*)&outb[(size_t)(m + 8) * NTOK + nn] =
                make_float2(c[mt][nt][2], c[mt][nt][3]);
        }
    }
}

// ---------------------------------------------------------------------------
// prep_qk: fp32 [b][ch][n] -> token-major bf16 hi/lo [b][h][n][64]
// ---------------------------------------------------------------------------
__global__ void prep_qk_kernel()
{
    __shared__ float t[32][33];
    const int z  = blockIdx.z;
    const int which = z & 1;
    const int bh = z >> 1;
    const int b  = bh >> 3;
    const int h  = bh & 7;
    const int n0 = blockIdx.x * 32;
    const int d0 = blockIdx.y * 32;

    const float* src = (which ? g_K : g_Q) + ((size_t)(b * CH + h * DQ + d0)) * NTOK;
    __nv_bfloat16* dh = (which ? g_Kth : g_Qth) + (size_t)bh * NTOK * DQ;
    __nv_bfloat16* dl = (which ? g_Ktl : g_Qtl) + (size_t)bh * NTOK * DQ;

    const int tx = threadIdx.x, ty = threadIdx.y;
#pragma unroll
    for (int i = 0; i < 32; i += 8)
        t[ty + i][tx] = src[(size_t)(ty + i) * NTOK + n0 + tx];
    __syncthreads();
#pragma unroll
    for (int i = 0; i < 32; i += 8) {
        const float v = t[tx][ty + i];
        const __nv_bfloat16 hh = __float2bfloat16(v);
        const size_t o = (size_t)(n0 + ty + i) * DQ + d0 + tx;
        dh[o] = hh;
        dl[o] = __float2bfloat16(v - __bfloat162float(hh));
    }
}

// prep_v: elementwise split, layout preserved.
__global__ void prep_v_kernel()
{
    const int idx = blockIdx.x * 256 + threadIdx.x;     // per float4
    float4 v = ((const float4*)g_V)[idx];
    __nv_bfloat16 h0 = __float2bfloat16(v.x), h1 = __float2bfloat16(v.y);
    __nv_bfloat16 h2 = __float2bfloat16(v.z), h3 = __float2bfloat16(v.w);
    __nv_bfloat162* vh = (__nv_bfloat162*)g_Vh;
    __nv_bfloat162* vl = (__nv_bfloat162*)g_Vl;
    vh[idx * 2]     = __nv_bfloat162{h0, h1};
    vh[idx * 2 + 1] = __nv_bfloat162{h2, h3};
    vl[idx * 2]     = __nv_bfloat162{
        __float2bfloat16(v.x - __bfloat162float(h0)),
        __float2bfloat16(v.y - __bfloat162float(h1))};
    vl[idx * 2 + 1] = __nv_bfloat162{
        __float2bfloat16(v.z - __bfloat162float(h2)),
        __float2bfloat16(v.w - __bfloat162float(h3))};
}

// ---------------------------------------------------------------------------
// Flash attention on mma.sync bf16 (FA2 register-resident P, 3-term splits).
// Block: 256 thr (8 warps x 16 q-rows), q-tile 128, K/V tiles 128 dbl-buffered.
// ---------------------------------------------------------------------------
#define AT_OFF_QH 0
#define AT_OFF_QL 18432
#define AT_OFF_K0 36864
#define AT_KSTAGE 36864           // Kh 18432 + Kl 18432
#define AT_OFF_V0 110592
#define AT_VSTAGE 34816           // Vh 17408 + Vl 17408
#define AT_SMEM   180224
#define AT_OFF_EPI 36864          // fp32 [64][132] after mainloop

__global__ __launch_bounds__(256, 1) void attn_mma_kernel(
    const float* __restrict__ gamma, float* __restrict__ outp)
{
    extern __shared__ char sm[];
    const uint32_t sb = smem_u32(sm);
    const int tid = threadIdx.x, wid = tid >> 5, lid = tid & 31;
    const int q0 = blockIdx.x * 128, h = blockIdx.y, b = blockIdx.z;
    const int bh = b * HEADS + h;

    const __nv_bfloat16* Qh = g_Qth + (size_t)bh * NTOK * DQ;
    const __nv_bfloat16* Ql = g_Qtl + (size_t)bh * NTOK * DQ;
    const __nv_bfloat16* Kh = g_Kth + (size_t)bh * NTOK * DQ;
    const __nv_bfloat16* Kl = g_Ktl + (size_t)bh * NTOK * DQ;
    const __nv_bfloat16* Vh = g_Vh + (size_t)(b * CH + h * DQ) * NTOK;
    const __nv_bfloat16* Vl = g_Vl + (size_t)(b * CH + h * DQ) * NTOK;
    const float* SC = g_SC + (size_t)(b * CH + h * DQ) * NTOK;

    auto load_stage = [&](int st, int kt) {
        const int m0 = kt * 128;
        const uint32_t kdst = sb + AT_OFF_K0 + st * AT_KSTAGE;
        const uint32_t vdst = sb + AT_OFF_V0 + st * AT_VSTAGE;
#pragma unroll
        for (int j = 0; j < 16; j++) {
            const int idx = tid + j * 256;              // 0..4095
            if (idx < 2048) {
                const int hl = idx >> 10, i = idx & 1023;
                const int r = i >> 3, cc = i & 7;
                const __nv_bfloat16* s = (hl ? Kl : Kh) + (size_t)(m0 + r) * DQ + cc * 8;
                cp_async16(kdst + hl * 18432 + r * 144 + cc * 16, s);
            } else {
                const int t = idx & 2047;
                const int hl = t >> 10, i = t & 1023;
                const int dv = i >> 4, cc = i & 15;
                const __nv_bfloat16* s = (hl ? Vl : Vh) + (size_t)dv * NTOK + m0 + cc * 8;
                cp_async16(vdst + hl * 17408 + dv * 272 + cc * 16, s);
            }
        }
    };

    // enqueue Q (token-major rows of 128B) + stage 0, one commit group
#pragma unroll
    for (int j = 0; j < 8; j++) {
        const int idx = tid + j * 256;                  // 0..2047
        const int hl = idx >> 10, i = idx & 1023;
        const int r = i >> 3, cc = i & 7;
        const __nv_bfloat16* s = (hl ? Ql : Qh) + (size_t)(q0 + r) * DQ + cc * 8;
        cp_async16(sb + (hl ? AT_OFF_QL : AT_OFF_QH) + r * 144 + cc * 16, s);
    }
    load_stage(0, 0);
    cp_commit();

    const int qw = wid * 16;
    const int arow = (lid & 7) + ((lid & 8) ? 8 : 0);
    const int akob = (lid & 16) ? 16 : 0;
    const int brow = (lid & 7) + ((lid & 16) ? 8 : 0);
    const int bkob = (lid & 8) ? 16 : 0;

    uint32_t qa_h[4][4], qa_l[4][4];
    float acc[8][4];
#pragma unroll
    for (int t = 0; t < 8; t++)
#pragma unroll
        for (int k = 0; k < 4; k++) acc[t][k] = 0.f;
    float m0_ = -1e30f, m1_ = -1e30f, l0_ = 0.f, l1_ = 0.f;

    for (int kt = 0; kt < NTOK / 128; kt++) {
        const int st = kt & 1;
        if (kt + 1 < NTOK / 128) {
            load_stage(st ^ 1, kt + 1);
            cp_commit();
            cp_wait<1>();
        } else {
            cp_wait<0>();
        }
        __syncthreads();

        if (kt == 0) {
#pragma unroll
            for (int g = 0; g < 4; g++) {
                const uint32_t a = sb + AT_OFF_QH + (qw + arow) * 144 + akob + g * 32;
                ldsm4(qa_h[g][0], qa_h[g][1], qa_h[g][2], qa_h[g][3], a);
                ldsm4(qa_l[g][0], qa_l[g][1], qa_l[g][2], qa_l[g][3], a + 18432);
            }
        }

        // ---- GEMM1: S = Q K^T (3-term)
        float s[16][4];
#pragma unroll
        for (int t = 0; t < 16; t++)
#pragma unroll
            for (int k = 0; k < 4; k++) s[t][k] = 0.f;

        const uint32_t kb = sb + AT_OFF_K0 + st * AT_KSTAGE;
#pragma unroll
        for (int g = 0; g < 4; g++) {
#pragma unroll
            for (int tp = 0; tp < 8; tp++) {
                const uint32_t a = kb + (tp * 16 + brow) * 144 + bkob + g * 32;
                uint32_t kh0, kh1, kh2, kh3, kl0, kl1, kl2, kl3;
                ldsm4(kh0, kh1, kh2, kh3, a);
                ldsm4(kl0, kl1, kl2, kl3, a + 18432);
                mma_bf16(s[2*tp][0], s[2*tp][1], s[2*tp][2], s[2*tp][3],
                         qa_h[g][0], qa_h[g][1], qa_h[g][2], qa_h[g][3], kh0, kh1);
                mma_bf16(s[2*tp][0], s[2*tp][1], s[2*tp][2], s[2*tp][3],
                         qa_h[g][0], qa_h[g][1], qa_h[g][2], qa_h[g][3], kl0, kl1);
                mma_bf16(s[2*tp][0], s[2*tp][1], s[2*tp][2], s[2*tp][3],
                         qa_l[g][0], qa_l[g][1], qa_l[g][2], qa_l[g][3], kh0, kh1);
                mma_bf16(s[2*tp+1][0], s[2*tp+1][1], s[2*tp+1][2], s[2*tp+1][3],
                         qa_h[g][0], qa_h[g][1], qa_h[g][2], qa_h[g][3], kh2, kh3);
                mma_bf16(s[2*tp+1][0], s[2*tp+1][1], s[2*tp+1][2], s[2*tp+1][3],
                         qa_h[g][0], qa_h[g][1], qa_h[g][2], qa_h[g][3], kl2, kl3);
                mma_bf16(s[2*tp+1][0], s[2*tp+1][1], s[2*tp+1][2], s[2*tp+1][3],
                         qa_l[g][0], qa_l[g][1], qa_l[g][2], qa_l[g][3], kh2, kh3);
            }
        }

        // ---- online softmax on fragments (rows r0=lid>>2, r1=r0+8)
        float mx0 = -1e30f, mx1 = -1e30f;
#pragma unroll
        for (int t = 0; t < 16; t++) {
            mx0 = fmaxf(mx0, fmaxf(s[t][0], s[t][1]));
            mx1 = fmaxf(mx1, fmaxf(s[t][2], s[t][3]));
        }
        mx0 = fmaxf(mx0, __shfl_xor_sync(0xffffffffu, mx0, 1));
        mx0 = fmaxf(mx0, __shfl_xor_sync(0xffffffffu, mx0, 2));
        mx1 = fmaxf(mx1, __shfl_xor_sync(0xffffffffu, mx1, 1));
        mx1 = fmaxf(mx1, __shfl_xor_sync(0xffffffffu, mx1, 2));

        const float mn0 = fmaxf(m0_, mx0), mn1 = fmaxf(m1_, mx1);
        const float al0 = __expf(m0_ - mn0), al1 = __expf(m1_ - mn1);
        float sum0 = 0.f, sum1 = 0.f;
#pragma unroll
        for (int t = 0; t < 16; t++) {
            s[t][0] = __expf(s[t][0] - mn0); sum0 += s[t][0];
            s[t][1] = __expf(s[t][1] - mn0); sum0 += s[t][1];
            s[t][2] = __expf(s[t][2] - mn1); sum1 += s[t][2];
            s[t][3] = __expf(s[t][3] - mn1); sum1 += s[t][3];
        }
        sum0 += __shfl_xor_sync(0xffffffffu, sum0, 1);
        sum0 += __shfl_xor_sync(0xffffffffu, sum0, 2);
        sum1 += __shfl_xor_sync(0xffffffffu, sum1, 1);
        sum1 += __shfl_xor_sync(0xffffffffu, sum1, 2);

        l0_ = l0_ * al0 + sum0;  l1_ = l1_ * al1 + sum1;
        m0_ = mn0;  m1_ = mn1;
#pragma unroll
        for (int t = 0; t < 8; t++) {
            acc[t][0] *= al0; acc[t][1] *= al0;
            acc[t][2] *= al1; acc[t][3] *= al1;
        }

        // ---- GEMM2: acc += P V (P hi/lo packed from fragments, 3-term)
        const uint32_t vb = sb + AT_OFF_V0 + st * AT_VSTAGE;
#pragma unroll
        for (int g = 0; g < 8; g++) {
            uint32_t ph[4], pl[4];
#pragma unroll
            for (int half = 0; half < 2; half++) {
                const float p0 = s[2*g + half][0], p1 = s[2*g + half][1];
                const float p2 = s[2*g + half][2], p3 = s[2*g + half][3];
                const uint32_t h01 = pack_bf16x2(p0, p1);
                const uint32_t h23 = pack_bf16x2(p2, p3);
                ph[half ? 2 : 0] = h01;
                ph[half ? 3 : 1] = h23;
                pl[half ? 2 : 0] = pack_bf16x2(
                    p0 - __uint_as_float(h01 << 16),
                    p1 - __uint_as_float(h01 & 0xffff0000u));
                pl[half ? 3 : 1] = pack_bf16x2(
                    p2 - __uint_as_float(h23 << 16),
                    p3 - __uint_as_float(h23 & 0xffff0000u));
            }
#pragma unroll
            for (int dvp = 0; dvp < 4; dvp++) {
                const uint32_t a = vb + (dvp * 16 + brow) * 272 + bkob + g * 32;
                uint32_t vh0, vh1, vh2, vh3, vl0, vl1, vl2, vl3;
                ldsm4(vh0, vh1, vh2, vh3, a);
                ldsm4(vl0, vl1, vl2, vl3, a + 17408);
                mma_bf16(acc[2*dvp][0], acc[2*dvp][1], acc[2*dvp][2], acc[2*dvp][3],
                         ph[0], ph[1], ph[2], ph[3], vh0, vh1);
                mma_bf16(acc[2*dvp][0], acc[2*dvp][1], acc[2*dvp][2], acc[2*dvp][3],
                         ph[0], ph[1], ph[2], ph[3], vl0, vl1);
                mma_bf16(acc[2*dvp][0], acc[2*dvp][1], acc[2*dvp][2], acc[2*dvp][3],
                         pl[0], pl[1], pl[2], pl[3], vh0, vh1);
                mma_bf16(acc[2*dvp+1][0], acc[2*dvp+1][1], acc[2*dvp+1][2], acc[2*dvp+1][3],
                         ph[0], ph[1], ph[2], ph[3], vh2, vh3);
                mma_bf16(acc[2*dvp+1][0], acc[2*dvp+1][1], acc[2*dvp+1][2], acc[2*dvp+1][3],
                         ph[0], ph[1], ph[2], ph[3], vl2, vl3);
                mma_bf16(acc[2*dvp+1][0], acc[2*dvp+1][1], acc[2*dvp+1][2], acc[2*dvp+1][3],
                         pl[0], pl[1], pl[2], pl[3], vh2, vh3);
            }
        }
        __syncthreads();
    }

    // ---- epilogue: acc/l -> smem [dv][132] -> fused gamma*out + sc stores
    const float inv0 = 1.f / l0_, inv1 = 1.f / l1_;
    float* epi = (float*)(sm + AT_OFF_EPI);
    const int qr = qw + (lid >> 2);
#pragma unroll
    for (int t = 0; t < 8; t++) {
        const int dv = t * 8 + 2 * (lid & 3);
        epi[dv * 132 + qr]           = acc[t][0] * inv0;
        epi[(dv + 1) * 132 + qr]     = acc[t][1] * inv0;
        epi[dv * 132 + qr + 8]       = acc[t][2] * inv1;
        epi[(dv + 1) * 132 + qr + 8] = acc[t][3] * inv1;
    }
    __syncthreads();

#pragma unroll
    for (int j = 0; j < 8; j++) {
        const int idx = tid + j * 256;          // 0..2047 float4s
        const int r = idx >> 5;                 // dv 0..63
        const int c4 = (idx & 31) * 4;
        const int ch = h * DQ + r;
        const float g = gamma[ch];
        float4 v = make_float4(epi[r * 132 + c4],     epi[r * 132 + c4 + 1],
                               epi[r * 132 + c4 + 2], epi[r * 132 + c4 + 3]);
        float4 scv = *(const float4*)&SC[(size_t)r * NTOK + q0 + c4];
        float4 o = make_float4(g * v.x + scv.x, g * v.y + scv.y,
                               g * v.z + scv.z, g * v.w + scv.w);
        *(float4*)&outp[((size_t)b * CH + ch) * NTOK + q0 + c4] = o;
    }
}

// ---------------------------------------------------------------------------
extern "C" void kernel_launch(void* const* d_in, const int* in_sizes, int n_in,
                              void* d_out, int out_size)
{
    const float* x     = (const float*)d_in[0];
    const float* Wq    = (const float*)d_in[1];
    const float* Wk    = (const float*)d_in[2];
    const float* Wv    = (const float*)d_in[3];
    const float* Wsc   = (const float*)d_in[4];
    const float* gamma = (const float*)d_in[5];
    float* out = (float*)d_out;

    prep_w_kernel<<<dim3(CH * CH / 256, 4), 256>>>(Wq, Wk, Wv, Wsc);
    prep_x_kernel<<<dim3(NTOK / 32, CH / 32, BATCH), dim3(32, 8)>>>(x);

    cudaFuncSetAttribute(proj_mma_kernel, cudaFuncAttributeMaxDynamicSharedMemorySize,
                         PJ_SMEM_BYTES);
    proj_mma_kernel<<<dim3(NTOK / 128, CH / 128, 16), 256, PJ_SMEM_BYTES>>>();

    prep_qk_kernel<<<dim3(NTOK / 32, DQ / 32, BATCH * HEADS * 2), dim3(32, 8)>>>();
    prep_v_kernel<<<BATCH * CH * NTOK / 1024, 256>>>();

    cudaFuncSetAttribute(attn_mma_kernel, cudaFuncAttributeMaxDynamicSharedMemorySize,
                         AT_SMEM);
    attn_mma_kernel<<<dim3(NTOK / 128, HEADS, BATCH), 256, AT_SMEM>>>(gamma, out);
}

// round 8
// speedup vs baseline: 4.1738x; 1.0335x over previous
#include <cuda_runtime.h>
#include <cuda_bf16.h>
#include <math.h>
#include <stdint.h>

#define HEADS 8
#define BATCH 4
#define CH    512
#define NTOK  2304          // 48*48
#define DQ    64

// Scratch (allocation-free rule: __device__ globals)
__device__ float g_SC[BATCH * CH * NTOK];
__device__ __nv_bfloat16 g_Wh [4 * CH * CH];
__device__ __nv_bfloat16 g_Wl [4 * CH * CH];
__device__ __nv_bfloat16 g_xth[BATCH * NTOK * CH];
__device__ __nv_bfloat16 g_xtl[BATCH * NTOK * CH];
// token-major bf16 hi/lo Q,K: [b][h][n][64]
__device__ __nv_bfloat16 g_Qth[BATCH * HEADS * NTOK * DQ];
__device__ __nv_bfloat16 g_Qtl[BATCH * HEADS * NTOK * DQ];
__device__ __nv_bfloat16 g_Kth[BATCH * HEADS * NTOK * DQ];
__device__ __nv_bfloat16 g_Ktl[BATCH * HEADS * NTOK * DQ];
// V split: [b][ch][n]
__device__ __nv_bfloat16 g_Vh[BATCH * CH * NTOK];
__device__ __nv_bfloat16 g_Vl[BATCH * CH * NTOK];

// ---------------------------------------------------------------------------
// PTX helpers (compute_100-safe: cp.async, ldmatrix, mma.sync)
// ---------------------------------------------------------------------------
__device__ __forceinline__ void cp_async16(uint32_t dst, const void* src) {
    asm volatile("cp.async.cg.shared.global [%0], [%1], 16;\n" :: "r"(dst), "l"(src));
}
__device__ __forceinline__ void cp_commit() {
    asm volatile("cp.async.commit_group;\n" ::);
}
template<int N> __device__ __forceinline__ void cp_wait() {
    asm volatile("cp.async.wait_group %0;\n" :: "n"(N));
}
__device__ __forceinline__ uint32_t smem_u32(const void* p) {
    return (uint32_t)__cvta_generic_to_shared(p);
}
__device__ __forceinline__ void ldsm4(uint32_t& r0, uint32_t& r1, uint32_t& r2,
                                      uint32_t& r3, uint32_t a) {
    asm volatile("ldmatrix.sync.aligned.m8n8.x4.shared.b16 {%0,%1,%2,%3}, [%4];"
                 : "=r"(r0), "=r"(r1), "=r"(r2), "=r"(r3) : "r"(a));
}
__device__ __forceinline__ void ldsm2(uint32_t& r0, uint32_t& r1, uint32_t a) {
    asm volatile("ldmatrix.sync.aligned.m8n8.x2.shared.b16 {%0,%1}, [%2];"
                 : "=r"(r0), "=r"(r1) : "r"(a));
}
__device__ __forceinline__ void mma_bf16(float& c0, float& c1, float& c2, float& c3,
                                         uint32_t a0, uint32_t a1, uint32_t a2, uint32_t a3,
                                         uint32_t b0, uint32_t b1) {
    asm volatile("mma.sync.aligned.m16n8k16.row.col.f32.bf16.bf16.f32 "
                 "{%0,%1,%2,%3}, {%4,%5,%6,%7}, {%8,%9}, {%0,%1,%2,%3};"
                 : "+f"(c0), "+f"(c1), "+f"(c2), "+f"(c3)
                 : "r"(a0), "r"(a1), "r"(a2), "r"(a3), "r"(b0), "r"(b1));
}
// packs (lo -> lower 16, hi -> upper 16), rn rounding
__device__ __forceinline__ uint32_t pack_bf16x2(float lo, float hi) {
    uint32_t r;
    asm("cvt.rn.bf16x2.f32 %0, %1, %2;" : "=r"(r) : "f"(hi), "f"(lo));
    return r;
}

// ---------------------------------------------------------------------------
// prep kernels: bf16 hi/lo split of W; x transposed to [b][n][c] hi/lo
// ---------------------------------------------------------------------------
__global__ void prep_w_kernel(const float* __restrict__ Wq, const float* __restrict__ Wk,
                              const float* __restrict__ Wv, const float* __restrict__ Wsc)
{
    const float* W = (blockIdx.y == 0) ? Wq : (blockIdx.y == 1) ? Wk
                   : (blockIdx.y == 2) ? Wv : Wsc;
    const int idx = blockIdx.x * 256 + threadIdx.x;
    const float a = W[idx];
    const __nv_bfloat16 h = __float2bfloat16(a);
    const size_t o = (size_t)blockIdx.y * CH * CH + idx;
    g_Wh[o] = h;
    g_Wl[o] = __float2bfloat16(a - __bfloat162float(h));
}

__global__ void prep_x_kernel(const float* __restrict__ x)
{
    __shared__ float t[32][33];
    const int b  = blockIdx.z;
    const int n0 = blockIdx.x * 32;
    const int c0 = blockIdx.y * 32;
    const int tx = threadIdx.x, ty = threadIdx.y;
    const float* src = x + ((size_t)b * CH + c0) * NTOK + n0;
#pragma unroll
    for (int i = 0; i < 32; i += 8)
        t[ty + i][tx] = src[(size_t)(ty + i) * NTOK + tx];
    __syncthreads();
    __nv_bfloat16* dh = g_xth + ((size_t)b * NTOK + n0) * CH + c0;
    __nv_bfloat16* dl = g_xtl + ((size_t)b * NTOK + n0) * CH + c0;
#pragma unroll
    for (int i = 0; i < 32; i += 8) {
        const float v = t[tx][ty + i];
        const __nv_bfloat16 h = __float2bfloat16(v);
        dh[(size_t)(ty + i) * CH + tx] = h;
        dl[(size_t)(ty + i) * CH + tx] = __float2bfloat16(v - __bfloat162float(h));
    }
}

// ---------------------------------------------------------------------------
// Projection GEMM via mma.sync bf16 3-term split, with FUSED output formatting:
//   which 0/1 (Q/K): token-major bf16 hi/lo [b][h][n][64]
//   which 2   (V)  : bf16 hi/lo [b][ch][n]
//   which 3   (SC) : fp32 [b][ch][n]
// ---------------------------------------------------------------------------
#define PJ_ARR_BYTES   10240
#define PJ_STAGE_BYTES (4 * PJ_ARR_BYTES)
#define PJ_SMEM_BYTES  (2 * PJ_STAGE_BYTES)   // 81920; epi [128][132] fp32 = 67584 fits

__global__ __launch_bounds__(256, 1) void proj_mma_kernel(void)
{
    extern __shared__ char smem[];
    const uint32_t sbase = smem_u32(smem);
    const int tid = threadIdx.x;
    const int wid = tid >> 5;
    const int lid = tid & 31;

    const int which = blockIdx.z & 3;
    const int b     = blockIdx.z >> 2;
    const int n0    = blockIdx.x * 128;
    const int o0    = blockIdx.y * 128;

    const __nv_bfloat16* Ah_g = g_Wh + (size_t)which * CH * CH + (size_t)o0 * CH;
    const __nv_bfloat16* Al_g = g_Wl + (size_t)which * CH * CH + (size_t)o0 * CH;
    const __nv_bfloat16* Bh_g = g_xth + ((size_t)b * NTOK + n0) * CH;
    const __nv_bfloat16* Bl_g = g_xtl + ((size_t)b * NTOK + n0) * CH;

    const int warp_m = wid >> 2;
    const int warp_n = wid & 3;
    const int mbase = warp_m * 64;
    const int nbase = warp_n * 32;

    auto load_chunk = [&](int buf, int chunk) {
        const int c0 = chunk * 32;
        const uint32_t sb = sbase + buf * PJ_STAGE_BYTES;
#pragma unroll
        for (int t = 0; t < 8; t++) {
            const int idx = tid + t * 256;
            const int arr = idx >> 9;
            const int i   = idx & 511;
            const int row = i >> 2;
            const int q16 = (i & 3) * 16;
            const uint32_t dst = sb + arr * PJ_ARR_BYTES + row * 80 + q16;
            const __nv_bfloat16* base = (arr == 0) ? Ah_g : (arr == 1) ? Al_g
                                      : (arr == 2) ? Bh_g : Bl_g;
            cp_async16(dst, (const char*)(base + (size_t)row * CH + c0) + q16);
        }
        cp_commit();
    };

    float c[4][4][4];
#pragma unroll
    for (int mt = 0; mt < 4; mt++)
#pragma unroll
        for (int nt = 0; nt < 4; nt++)
#pragma unroll
            for (int k = 0; k < 4; k++) c[mt][nt][k] = 0.f;

    load_chunk(0, 0);

    for (int chunk = 0; chunk < 16; chunk++) {
        const int buf = chunk & 1;
        if (chunk + 1 < 16) {
            load_chunk(buf ^ 1, chunk + 1);
            cp_wait<1>();
        } else {
            cp_wait<0>();
        }
        __syncthreads();

        const uint32_t sb = sbase + buf * PJ_STAGE_BYTES;
        const int arow = (lid & 7) + ((lid & 8) ? 8 : 0);
        const int akob = (lid & 16) ? 16 : 0;
        const int brow = lid & 7;
        const int bkob = (lid & 8) ? 16 : 0;

#pragma unroll
        for (int kstep = 0; kstep < 2; kstep++) {
            const int kb = kstep * 32;

            uint32_t bh[4][2], bl[4][2];
#pragma unroll
            for (int nt = 0; nt < 4; nt++) {
                const uint32_t ba = sb + 2 * PJ_ARR_BYTES +
                                    (nbase + nt * 8 + brow) * 80 + bkob + kb;
                ldsm2(bh[nt][0], bh[nt][1], ba);
                ldsm2(bl[nt][0], bl[nt][1], ba + PJ_ARR_BYTES);
            }

#pragma unroll
            for (int mt = 0; mt < 4; mt++) {
                const uint32_t aa = sb + (mbase + mt * 16 + arow) * 80 + akob + kb;
                uint32_t ah[4], al[4];
                ldsm4(ah[0], ah[1], ah[2], ah[3], aa);
                ldsm4(al[0], al[1], al[2], al[3], aa + PJ_ARR_BYTES);
#pragma unroll
                for (int nt = 0; nt < 4; nt++) {
                    mma_bf16(c[mt][nt][0], c[mt][nt][1], c[mt][nt][2], c[mt][nt][3],
                             ah[0], ah[1], ah[2], ah[3], bh[nt][0], bh[nt][1]);
                    mma_bf16(c[mt][nt][0], c[mt][nt][1], c[mt][nt][2], c[mt][nt][3],
                             ah[0], ah[1], ah[2], ah[3], bl[nt][0], bl[nt][1]);
                    mma_bf16(c[mt][nt][0], c[mt][nt][1], c[mt][nt][2], c[mt][nt][3],
                             al[0], al[1], al[2], al[3], bh[nt][0], bh[nt][1]);
                }
            }
        }
        __syncthreads();
    }

    // ---- fused epilogue: stage fp32 tile in smem [128 m][132], then format
    float* epi = (float*)smem;
#pragma unroll
    for (int mt = 0; mt < 4; mt++) {
#pragma unroll
        for (int nt = 0; nt < 4; nt++) {
            const int m = mbase + mt * 16 + (lid >> 2);
            const int nn = nbase + nt * 8 + 2 * (lid & 3);
            epi[m * 132 + nn]           = c[mt][nt][0];
            epi[m * 132 + nn + 1]       = c[mt][nt][1];
            epi[(m + 8) * 132 + nn]     = c[mt][nt][2];
            epi[(m + 8) * 132 + nn + 1] = c[mt][nt][3];
        }
    }
    __syncthreads();

    if (which == 3) {
        // SC: fp32 coalesced — FULL tile: 4096 float4s (j < 16)
        float* outb = g_SC + ((size_t)b * CH + o0) * NTOK + n0;
#pragma unroll
        for (int j = 0; j < 16; j++) {
            const int idx = tid + j * 256;          // 0..4095
            const int m  = idx >> 5;                // 0..127
            const int n4 = (idx & 31) * 4;
            float4 v = make_float4(epi[m * 132 + n4],     epi[m * 132 + n4 + 1],
                                   epi[m * 132 + n4 + 2], epi[m * 132 + n4 + 3]);
            *(float4*)&outb[(size_t)m * NTOK + n4] = v;
        }
    } else if (which == 2) {
        // V: bf16 hi/lo — FULL tile: 4096 uint2s (j < 16)
        __nv_bfloat16* vh = g_Vh + ((size_t)b * CH + o0) * NTOK + n0;
        __nv_bfloat16* vl = g_Vl + ((size_t)b * CH + o0) * NTOK + n0;
#pragma unroll
        for (int j = 0; j < 16; j++) {
            const int idx = tid + j * 256;          // 0..4095
            const int m  = idx >> 5;                // 0..127
            const int n4 = (idx & 31) * 4;
            const float v0 = epi[m * 132 + n4],     v1 = epi[m * 132 + n4 + 1];
            const float v2 = epi[m * 132 + n4 + 2], v3 = epi[m * 132 + n4 + 3];
            const uint32_t h01 = pack_bf16x2(v0, v1);
            const uint32_t h23 = pack_bf16x2(v2, v3);
            const uint32_t l01 = pack_bf16x2(v0 - __uint_as_float(h01 << 16),
                                             v1 - __uint_as_float(h01 & 0xffff0000u));
            const uint32_t l23 = pack_bf16x2(v2 - __uint_as_float(h23 << 16),
                                             v3 - __uint_as_float(h23 & 0xffff0000u));
            *(uint2*)(vh + (size_t)m * NTOK + n4) = make_uint2(h01, h23);
            *(uint2*)(vl + (size_t)m * NTOK + n4) = make_uint2(l01, l23);
        }
    } else {
        // Q or K: token-major bf16 hi/lo [bh][n][64]. 256 threads = 128 tokens x 2 heads.
        const int tok = tid >> 1;
        const int hp  = tid & 1;
        const int head = (o0 >> 6) + hp;            // o0/64 = 2*blockIdx.y
        __nv_bfloat16* qh = ((which == 0) ? g_Qth : g_Kth) +
            ((size_t)(b * HEADS + head) * NTOK + n0 + tok) * DQ;
        __nv_bfloat16* ql = ((which == 0) ? g_Qtl : g_Ktl) +
            ((size_t)(b * HEADS + head) * NTOK + n0 + tok) * DQ;
#pragma unroll
        for (int g8 = 0; g8 < 8; g8++) {
            uint32_t hw[4], lw[4];
#pragma unroll
            for (int p = 0; p < 4; p++) {
                const int d = g8 * 8 + p * 2;
                const float v0 = epi[(hp * 64 + d) * 132 + tok];
                const float v1 = epi[(hp * 64 + d + 1) * 132 + tok];
                const uint32_t hh = pack_bf16x2(v0, v1);
                hw[p] = hh;
                lw[p] = pack_bf16x2(v0 - __uint_as_float(hh << 16),
                                    v1 - __uint_as_float(hh & 0xffff0000u));
            }
            ((uint4*)qh)[g8] = make_uint4(hw[0], hw[1], hw[2], hw[3]);
            ((uint4*)ql)[g8] = make_uint4(lw[0], lw[1], lw[2], lw[3]);
        }
    }
}

// ---------------------------------------------------------------------------
// Flash attention on mma.sync bf16 (FA2 register-resident P, 3-term splits).
// Block: 256 thr (8 warps x 16 q-rows), q-tile 128, K/V tiles 128 dbl-buffered.
// ---------------------------------------------------------------------------
#define AT_OFF_QH 0
#define AT_OFF_QL 18432
#define AT_OFF_K0 36864
#define AT_KSTAGE 36864           // Kh 18432 + Kl 18432
#define AT_OFF_V0 110592
#define AT_VSTAGE 34816           // Vh 17408 + Vl 17408
#define AT_SMEM   180224
#define AT_OFF_EPI 36864          // fp32 [64][132] after mainloop

__global__ __launch_bounds__(256, 1) void attn_mma_kernel(
    const float* __restrict__ gamma, float* __restrict__ outp)
{
    extern __shared__ char sm[];
    const uint32_t sb = smem_u32(sm);
    const int tid = threadIdx.x, wid = tid >> 5, lid = tid & 31;
    const int q0 = blockIdx.x * 128, h = blockIdx.y, b = blockIdx.z;
    const int bh = b * HEADS + h;

    const __nv_bfloat16* Qh = g_Qth + (size_t)bh * NTOK * DQ;
    const __nv_bfloat16* Ql = g_Qtl + (size_t)bh * NTOK * DQ;
    const __nv_bfloat16* Kh = g_Kth + (size_t)bh * NTOK * DQ;
    const __nv_bfloat16* Kl = g_Ktl + (size_t)bh * NTOK * DQ;
    const __nv_bfloat16* Vh = g_Vh + (size_t)(b * CH + h * DQ) * NTOK;
    const __nv_bfloat16* Vl = g_Vl + (size_t)(b * CH + h * DQ) * NTOK;
    const float* SC = g_SC + (size_t)(b * CH + h * DQ) * NTOK;

    auto load_stage = [&](int st, int kt) {
        const int m0 = kt * 128;
        const uint32_t kdst = sb + AT_OFF_K0 + st * AT_KSTAGE;
        const uint32_t vdst = sb + AT_OFF_V0 + st * AT_VSTAGE;
#pragma unroll
        for (int j = 0; j < 16; j++) {
            const int idx = tid + j * 256;              // 0..4095
            if (idx < 2048) {
                const int hl = idx >> 10, i = idx & 1023;
                const int r = i >> 3, cc = i & 7;
                const __nv_bfloat16* s = (hl ? Kl : Kh) + (size_t)(m0 + r) * DQ + cc * 8;
                cp_async16(kdst + hl * 18432 + r * 144 + cc * 16, s);
            } else {
                const int t = idx & 2047;
                const int hl = t >> 10, i = t & 1023;
                const int dv = i >> 4, cc = i & 15;
                const __nv_bfloat16* s = (hl ? Vl : Vh) + (size_t)dv * NTOK + m0 + cc * 8;
                cp_async16(vdst + hl * 17408 + dv * 272 + cc * 16, s);
            }
        }
    };

    // enqueue Q + stage 0, one commit group
#pragma unroll
    for (int j = 0; j < 8; j++) {
        const int idx = tid + j * 256;                  // 0..2047
        const int hl = idx >> 10, i = idx & 1023;
        const int r = i >> 3, cc = i & 7;
        const __nv_bfloat16* s = (hl ? Ql : Qh) + (size_t)(q0 + r) * DQ + cc * 8;
        cp_async16(sb + (hl ? AT_OFF_QL : AT_OFF_QH) + r * 144 + cc * 16, s);
    }
    load_stage(0, 0);
    cp_commit();

    const int qw = wid * 16;
    const int arow = (lid & 7) + ((lid & 8) ? 8 : 0);
    const int akob = (lid & 16) ? 16 : 0;
    const int brow = (lid & 7) + ((lid & 16) ? 8 : 0);
    const int bkob = (lid & 8) ? 16 : 0;

    uint32_t qa_h[4][4], qa_l[4][4];
    float acc[8][4];
#pragma unroll
    for (int t = 0; t < 8; t++)
#pragma unroll
        for (int k = 0; k < 4; k++) acc[t][k] = 0.f;
    float m0_ = -1e30f, m1_ = -1e30f, l0_ = 0.f, l1_ = 0.f;

    for (int kt = 0; kt < NTOK / 128; kt++) {
        const int st = kt & 1;
        if (kt + 1 < NTOK / 128) {
            load_stage(st ^ 1, kt + 1);
            cp_commit();
            cp_wait<1>();
        } else {
            cp_wait<0>();
        }
        __syncthreads();

        if (kt == 0) {
#pragma unroll
            for (int g = 0; g < 4; g++) {
                const uint32_t a = sb + AT_OFF_QH + (qw + arow) * 144 + akob + g * 32;
                ldsm4(qa_h[g][0], qa_h[g][1], qa_h[g][2], qa_h[g][3], a);
                ldsm4(qa_l[g][0], qa_l[g][1], qa_l[g][2], qa_l[g][3], a + 18432);
            }
        }

        // ---- GEMM1: S = Q K^T (3-term)
        float s[16][4];
#pragma unroll
        for (int t = 0; t < 16; t++)
#pragma unroll
            for (int k = 0; k < 4; k++) s[t][k] = 0.f;

        const uint32_t kb = sb + AT_OFF_K0 + st * AT_KSTAGE;
#pragma unroll
        for (int g = 0; g < 4; g++) {
#pragma unroll
            for (int tp = 0; tp < 8; tp++) {
                const uint32_t a = kb + (tp * 16 + brow) * 144 + bkob + g * 32;
                uint32_t kh0, kh1, kh2, kh3, kl0, kl1, kl2, kl3;
                ldsm4(kh0, kh1, kh2, kh3, a);
                ldsm4(kl0, kl1, kl2, kl3, a + 18432);
                mma_bf16(s[2*tp][0], s[2*tp][1], s[2*tp][2], s[2*tp][3],
                         qa_h[g][0], qa_h[g][1], qa_h[g][2], qa_h[g][3], kh0, kh1);
                mma_bf16(s[2*tp][0], s[2*tp][1], s[2*tp][2], s[2*tp][3],
                         qa_h[g][0], qa_h[g][1], qa_h[g][2], qa_h[g][3], kl0, kl1);
                mma_bf16(s[2*tp][0], s[2*tp][1], s[2*tp][2], s[2*tp][3],
                         qa_l[g][0], qa_l[g][1], qa_l[g][2], qa_l[g][3], kh0, kh1);
                mma_bf16(s[2*tp+1][0], s[2*tp+1][1], s[2*tp+1][2], s[2*tp+1][3],
                         qa_h[g][0], qa_h[g][1], qa_h[g][2], qa_h[g][3], kh2, kh3);
                mma_bf16(s[2*tp+1][0], s[2*tp+1][1], s[2*tp+1][2], s[2*tp+1][3],
                         qa_h[g][0], qa_h[g][1], qa_h[g][2], qa_h[g][3], kl2, kl3);
                mma_bf16(s[2*tp+1][0], s[2*tp+1][1], s[2*tp+1][2], s[2*tp+1][3],
                         qa_l[g][0], qa_l[g][1], qa_l[g][2], qa_l[g][3], kh2, kh3);
            }
        }

        // ---- online softmax on fragments
        float mx0 = -1e30f, mx1 = -1e30f;
#pragma unroll
        for (int t = 0; t < 16; t++) {
            mx0 = fmaxf(mx0, fmaxf(s[t][0], s[t][1]));
            mx1 = fmaxf(mx1, fmaxf(s[t][2], s[t][3]));
        }
        mx0 = fmaxf(mx0, __shfl_xor_sync(0xffffffffu, mx0, 1));
        mx0 = fmaxf(mx0, __shfl_xor_sync(0xffffffffu, mx0, 2));
        mx1 = fmaxf(mx1, __shfl_xor_sync(0xffffffffu, mx1, 1));
        mx1 = fmaxf(mx1, __shfl_xor_sync(0xffffffffu, mx1, 2));

        const float mn0 = fmaxf(m0_, mx0), mn1 = fmaxf(m1_, mx1);
        const float al0 = __expf(m0_ - mn0), al1 = __expf(m1_ - mn1);
        float sum0 = 0.f, sum1 = 0.f;
#pragma unroll
        for (int t = 0; t < 16; t++) {
            s[t][0] = __expf(s[t][0] - mn0); sum0 += s[t][0];
            s[t][1] = __expf(s[t][1] - mn0); sum0 += s[t][1];
            s[t][2] = __expf(s[t][2] - mn1); sum1 += s[t][2];
            s[t][3] = __expf(s[t][3] - mn1); sum1 += s[t][3];
        }
        sum0 += __shfl_xor_sync(0xffffffffu, sum0, 1);
        sum0 += __shfl_xor_sync(0xffffffffu, sum0, 2);
        sum1 += __shfl_xor_sync(0xffffffffu, sum1, 1);
        sum1 += __shfl_xor_sync(0xffffffffu, sum1, 2);

        l0_ = l0_ * al0 + sum0;  l1_ = l1_ * al1 + sum1;
        m0_ = mn0;  m1_ = mn1;
#pragma unroll
        for (int t = 0; t < 8; t++) {
            acc[t][0] *= al0; acc[t][1] *= al0;
            acc[t][2] *= al1; acc[t][3] *= al1;
        }

        // ---- GEMM2: acc += P V (P hi/lo packed from fragments, 3-term)
        const uint32_t vb = sb + AT_OFF_V0 + st * AT_VSTAGE;
#pragma unroll
        for (int g = 0; g < 8; g++) {
            uint32_t ph[4], pl[4];
#pragma unroll
            for (int half = 0; half < 2; half++) {
                const float p0 = s[2*g + half][0], p1 = s[2*g + half][1];
                const float p2 = s[2*g + half][2], p3 = s[2*g + half][3];
                const uint32_t h01 = pack_bf16x2(p0, p1);
                const uint32_t h23 = pack_bf16x2(p2, p3);
                ph[half ? 2 : 0] = h01;
                ph[half ? 3 : 1] = h23;
                pl[half ? 2 : 0] = pack_bf16x2(
                    p0 - __uint_as_float(h01 << 16),
                    p1 - __uint_as_float(h01 & 0xffff0000u));
                pl[half ? 3 : 1] = pack_bf16x2(
                    p2 - __uint_as_float(h23 << 16),
                    p3 - __uint_as_float(h23 & 0xffff0000u));
            }
#pragma unroll
            for (int dvp = 0; dvp < 4; dvp++) {
                const uint32_t a = vb + (dvp * 16 + brow) * 272 + bkob + g * 32;
                uint32_t vh0, vh1, vh2, vh3, vl0, vl1, vl2, vl3;
                ldsm4(vh0, vh1, vh2, vh3, a);
                ldsm4(vl0, vl1, vl2, vl3, a + 17408);
                mma_bf16(acc[2*dvp][0], acc[2*dvp][1], acc[2*dvp][2], acc[2*dvp][3],
                         ph[0], ph[1], ph[2], ph[3], vh0, vh1);
                mma_bf16(acc[2*dvp][0], acc[2*dvp][1], acc[2*dvp][2], acc[2*dvp][3],
                         ph[0], ph[1], ph[2], ph[3], vl0, vl1);
                mma_bf16(acc[2*dvp][0], acc[2*dvp][1], acc[2*dvp][2], acc[2*dvp][3],
                         pl[0], pl[1], pl[2], pl[3], vh0, vh1);
                mma_bf16(acc[2*dvp+1][0], acc[2*dvp+1][1], acc[2*dvp+1][2], acc[2*dvp+1][3],
                         ph[0], ph[1], ph[2], ph[3], vh2, vh3);
                mma_bf16(acc[2*dvp+1][0], acc[2*dvp+1][1], acc[2*dvp+1][2], acc[2*dvp+1][3],
                         ph[0], ph[1], ph[2], ph[3], vl2, vl3);
                mma_bf16(acc[2*dvp+1][0], acc[2*dvp+1][1], acc[2*dvp+1][2], acc[2*dvp+1][3],
                         pl[0], pl[1], pl[2], pl[3], vh2, vh3);
            }
        }
        __syncthreads();
    }

    // ---- epilogue: acc/l -> smem [dv][132] -> fused gamma*out + sc stores
    const float inv0 = 1.f / l0_, inv1 = 1.f / l1_;
    float* epi = (float*)(sm + AT_OFF_EPI);
    const int qr = qw + (lid >> 2);
#pragma unroll
    for (int t = 0; t < 8; t++) {
        const int dv = t * 8 + 2 * (lid & 3);
        epi[dv * 132 + qr]           = acc[t][0] * inv0;
        epi[(dv + 1) * 132 + qr]     = acc[t][1] * inv0;
        epi[dv * 132 + qr + 8]       = acc[t][2] * inv1;
        epi[(dv + 1) * 132 + qr + 8] = acc[t][3] * inv1;
    }
    __syncthreads();

#pragma unroll
    for (int j = 0; j < 8; j++) {
        const int idx = tid + j * 256;          // 0..2047 float4s (64 dv x 32 q4)
        const int r = idx >> 5;                 // dv 0..63
        const int c4 = (idx & 31) * 4;
        const int ch = h * DQ + r;
        const float g = gamma[ch];
        float4 v = make_float4(epi[r * 132 + c4],     epi[r * 132 + c4 + 1],
                               epi[r * 132 + c4 + 2], epi[r * 132 + c4 + 3]);
        float4 scv = *(const float4*)&SC[(size_t)r * NTOK + q0 + c4];
        float4 o = make_float4(g * v.x + scv.x, g * v.y + scv.y,
                               g * v.z + scv.z, g * v.w + scv.w);
        *(float4*)&outp[((size_t)b * CH + ch) * NTOK + q0 + c4] = o;
    }
}

// ---------------------------------------------------------------------------
extern "C" void kernel_launch(void* const* d_in, const int* in_sizes, int n_in,
                              void* d_out, int out_size)
{
    const float* x     = (const float*)d_in[0];
    const float* Wq    = (const float*)d_in[1];
    const float* Wk    = (const float*)d_in[2];
    const float* Wv    = (const float*)d_in[3];
    const float* Wsc   = (const float*)d_in[4];
    const float* gamma = (const float*)d_in[5];
    float* out = (float*)d_out;

    prep_w_kernel<<<dim3(CH * CH / 256, 4), 256>>>(Wq, Wk, Wv, Wsc);
    prep_x_kernel<<<dim3(NTOK / 32, CH / 32, BATCH), dim3(32, 8)>>>(x);

    cudaFuncSetAttribute(proj_mma_kernel, cudaFuncAttributeMaxDynamicSharedMemorySize,
                         PJ_SMEM_BYTES);
    proj_mma_kernel<<<dim3(NTOK / 128, CH / 128, 16), 256, PJ_SMEM_BYTES>>>();

    cudaFuncSetAttribute(attn_mma_kernel, cudaFuncAttributeMaxDynamicSharedMemorySize,
                         AT_SMEM);
    attn_mma_kernel<<<dim3(NTOK / 128, HEADS, BATCH), 256, AT_SMEM>>>(gamma, out);
}